// round 8
// baseline (speedup 1.0000x reference)
#include <cuda_runtime.h>
#include <cuda_bf16.h>
#include <math.h>
#include <stdint.h>

// Problem constants
#define T_STEPS 512
#define B_SZ    64
#define F_SZ    128
#define H_SZ    512
#define O_SZ    16
#define G_SZ    (3 * H_SZ)   // 1536

// K2 config: 128 CTAs = 2 batch-groups x 64 j-blocks; CTA = 32 batches x 8 j
#define NCTA2   128
#define NTHR2   512
#define JPC     8
#define GRPCTA  64            // CTAs per batch-group

// K2 dynamic SMEM
#define BSM_U32     (2 * 3 * 32 * 32 * 2)   // 12288 u32 = 49152 B
#define DST         26                       // Dsm row stride (floats)
#define NSLOT       12
#define DSM_FLOATS  (NSLOT * 32 * DST)       // 9984
#define SMEM2_BYTES (BSM_U32 * 4 + DSM_FLOATS * 4)   // 89088

#define NTILES_A    2048      // (T*B)/16 m16 tiles of x
#define NTILES_WN   192       // 1536/8 n8 tiles of w_ih

// ---------------------------------------------------------------------------
// Device scratch
// ---------------------------------------------------------------------------
__device__ float g_XG[T_STEPS * B_SZ * G_SZ];       // input-side gate preacts
__device__ float g_HS[T_STEPS * B_SZ * H_SZ];       // hidden states (for K3)
// h in HMMA A-fragment layout: [buf][(mt*32 + ks)*128 + lane*4 + reg]
__device__ uint32_t g_Hfrag[2][8 * 32 * 128];
// prepacked x A-fragments: [part][(tile*8 + ks)*32 + lane] (uint4)
__device__ uint4 g_XF[2][NTILES_A * 8 * 32];
// prepacked w_ih B-fragments: [part][(ntg*8 + ks)*32 + lane] (uint2)
__device__ uint2 g_WF[2][NTILES_WN * 8 * 32];
__device__ __align__(128) unsigned g_arr2[2][32];   // per-group arrival counters
__device__ __align__(128) unsigned g_cnt2[2][32];   // per-group reset counters

// ---------------------------------------------------------------------------
// Helpers
// ---------------------------------------------------------------------------
__device__ __forceinline__ float fsig(float x) { return 1.0f / (1.0f + __expf(-x)); }
__device__ __forceinline__ float ftanh(float x) { return 2.0f / (1.0f + __expf(-2.0f * x)) - 1.0f; }

__device__ __forceinline__ uint32_t pkbf(float a, float b) {
    return (uint32_t)__bfloat16_as_ushort(__float2bfloat16(a))
         | ((uint32_t)__bfloat16_as_ushort(__float2bfloat16(b)) << 16);
}
__device__ __forceinline__ float bflo(float v) {
    return v - __bfloat162float(__float2bfloat16(v));
}

// mma.sync m16n8k16 row.col f32.bf16.bf16.f32
__device__ __forceinline__ void hmma(float* d, const uint4& a, uint32_t b0, uint32_t b1) {
    asm volatile(
        "mma.sync.aligned.m16n8k16.row.col.f32.bf16.bf16.f32 "
        "{%0,%1,%2,%3}, {%4,%5,%6,%7}, {%8,%9}, {%0,%1,%2,%3};"
        : "+f"(d[0]), "+f"(d[1]), "+f"(d[2]), "+f"(d[3])
        : "r"(a.x), "r"(a.y), "r"(a.z), "r"(a.w), "r"(b0), "r"(b1));
}

// ---------------------------------------------------------------------------
// k0: prepack x (A-frags) and w_ih (B-frags) as bf16 hi/lo.
// CTAs [0, 2048): one m16 x-tile each. CTAs [2048, 2240): one n8 w-tile each.
// ---------------------------------------------------------------------------
__global__ void __launch_bounds__(256, 4)
k0_pack(const float* __restrict__ x, const float* __restrict__ wih)
{
    const int tid  = threadIdx.x;
    const int ks   = tid >> 5;
    const int lane = tid & 31;
    const int cb   = blockIdx.x;

    if (cb < NTILES_A) {
        const int row0 = cb * 16 + (lane >> 2);
        const int kc   = ks * 16 + (lane & 3) * 2;
        const float* r0 = &x[row0 * F_SZ + kc];
        const float* r1 = r0 + 8 * F_SZ;
        float2 x00 = *(const float2*)r0;
        float2 x10 = *(const float2*)r1;
        float2 x01 = *(const float2*)(r0 + 8);
        float2 x11 = *(const float2*)(r1 + 8);
        int idx = (cb * 8 + ks) * 32 + lane;
        g_XF[0][idx] = make_uint4(pkbf(x00.x, x00.y), pkbf(x10.x, x10.y),
                                  pkbf(x01.x, x01.y), pkbf(x11.x, x11.y));
        g_XF[1][idx] = make_uint4(pkbf(bflo(x00.x), bflo(x00.y)),
                                  pkbf(bflo(x10.x), bflo(x10.y)),
                                  pkbf(bflo(x01.x), bflo(x01.y)),
                                  pkbf(bflo(x11.x), bflo(x11.y)));
    } else {
        const int ntg = cb - NTILES_A;
        const int n   = ntg * 8 + (lane >> 2);
        const int kc  = ks * 16 + (lane & 3) * 2;
        const float* wr = &wih[n * F_SZ + kc];
        float w00 = wr[0], w01 = wr[1], w10 = wr[8], w11 = wr[9];
        int idx = (ntg * 8 + ks) * 32 + lane;
        g_WF[0][idx] = make_uint2(pkbf(w00, w01), pkbf(w10, w11));
        g_WF[1][idx] = make_uint2(pkbf(bflo(w00), bflo(w01)),
                                  pkbf(bflo(w10), bflo(w11)));
    }
}

// ---------------------------------------------------------------------------
// K1: xg = x @ w_ih^T + b_ih via HMMA on prepacked fragments (SMEM-free).
// CTA 256 thr (8 warps), warp = one m16 tile; N tile = 64 (8 n8 tiles).
// ---------------------------------------------------------------------------
__global__ void __launch_bounds__(256, 3)
k1_xg(const float* __restrict__ bih)
{
    const int tid  = threadIdx.x;
    const int wid  = tid >> 5;
    const int lane = tid & 31;
    const int tile = blockIdx.y * 8 + wid;
    const int n0   = blockIdx.x * 64;
    const int ntb  = blockIdx.x * 8;

    float acc[8][4];
#pragma unroll
    for (int nt = 0; nt < 8; nt++)
#pragma unroll
        for (int i = 0; i < 4; i++) acc[nt][i] = 0.f;

#pragma unroll
    for (int ks = 0; ks < 8; ks++) {
        const int ai = (tile * 8 + ks) * 32 + lane;
        uint4 ahi = __ldg(&g_XF[0][ai]);
        uint4 alo = __ldg(&g_XF[1][ai]);
#pragma unroll
        for (int nt = 0; nt < 8; nt++) {
            const int bi = ((ntb + nt) * 8 + ks) * 32 + lane;
            uint2 bh = __ldg(&g_WF[0][bi]);
            uint2 bl = __ldg(&g_WF[1][bi]);
            hmma(acc[nt], ahi, bh.x, bh.y);
            hmma(acc[nt], alo, bh.x, bh.y);
            hmma(acc[nt], ahi, bl.x, bl.y);
        }
    }

    const int gid = lane >> 2;
    const int tig = lane & 3;
    const int row0 = tile * 16 + gid;
#pragma unroll
    for (int nt = 0; nt < 8; nt++) {
        int col = n0 + nt * 8 + tig * 2;
        float2 bb = *(const float2*)&bih[col];
        *(float2*)&g_XG[row0 * G_SZ + col] =
            make_float2(acc[nt][0] + bb.x, acc[nt][1] + bb.y);
        *(float2*)&g_XG[(row0 + 8) * G_SZ + col] =
            make_float2(acc[nt][2] + bb.x, acc[nt][3] + bb.y);
    }
}

// ---------------------------------------------------------------------------
// K2: persistent HMMA GRU recurrence, 2-D tiled (32 batches x 8 j per CTA),
// 16 warps (4/SMSP), K split 4-way per warp-job for latency hiding.
// Warps 0-7  ("hi"): A = own-batch h_hi, both W passes (hi, lo).
// Warps 8-15 ("lo"): A = own-batch h_lo, W_hi pass only.
// ---------------------------------------------------------------------------
__global__ void __launch_bounds__(NTHR2, 1)
k2_gru(const float* __restrict__ wHH, const float* __restrict__ bHH)
{
    extern __shared__ uint32_t sm[];
    uint32_t* Bsm = sm;
    float*    Dsm = (float*)(sm + BSM_U32);

    const int tid  = threadIdx.x;
    const int wid  = tid >> 5;
    const int lane = tid & 31;
    const int bid  = blockIdx.x;
    const int grp  = bid & 1;
    const int b0   = grp * 32;
    const int j0   = (bid >> 1) * JPC;

    // ---- one-time: W -> bf16 hi/lo fragments in SMEM (24 real cols) ----
    for (int idx = tid; idx < 2 * 3 * 32 * 32; idx += NTHR2) {
        int el = idx & 31;
        int ks = (idx >> 5) & 31;
        int nt = (idx >> 10) % 3;
        int p  = idx / (3 * 1024);
        int n  = nt * 8 + (el >> 2);
        int jl = n / 3, g = n % 3;
        const float* wr = &wHH[(g * H_SZ + j0 + jl) * H_SZ + ks * 16 + (el & 3) * 2];
        float w00 = wr[0], w01 = wr[1], w10 = wr[8], w11 = wr[9];
        if (p) { w00 = bflo(w00); w01 = bflo(w01); w10 = bflo(w10); w11 = bflo(w11); }
        int base = ((((p * 3 + nt) * 32) + ks) * 32 + el) * 2;
        Bsm[base    ] = pkbf(w00, w01);
        Bsm[base + 1] = pkbf(w10, w11);
    }

    // ---- epilogue state: threads 0-255 = (batch eb, j-local jl) ----
    const int eb = (tid >> 3) & 31;
    const int jl = tid & 7;
    float bR = 0.f, bZ = 0.f, bN = 0.f, hprev = 0.f;
    if (tid < 256) {
        bR = __ldg(&bHH[0 * H_SZ + j0 + jl]);
        bZ = __ldg(&bHH[1 * H_SZ + j0 + jl]);
        bN = __ldg(&bHH[2 * H_SZ + j0 + jl]);
    }
    __syncthreads();

    // ---- MMA warp constants ----
    const int isHi = (wid < 8);
    const int mtl  = (wid >> 2) & 1;
    const int kh   = wid & 3;
    const int mtg  = (isHi ? 0 : 4) + (b0 >> 4) + mtl;
    const int gid  = lane >> 2;
    const int tig  = lane & 3;

    unsigned* arr = &g_arr2[grp][0];

    for (int t = 0; t < T_STEPS; t++) {
        // prefetch xg (independent of h)
        float xr = 0.f, xz = 0.f, xn = 0.f;
        if (tid < 256) {
            const int gbase = (t * B_SZ + b0 + eb) * G_SZ + j0 + jl;
            xr = __ldg(&g_XG[gbase]);
            xz = __ldg(&g_XG[gbase + H_SZ]);
            xn = __ldg(&g_XG[gbase + 2 * H_SZ]);
        }

        if (t > 0) {
            // ---- group barrier ----
            if (tid == 0) {
                unsigned target = (unsigned)GRPCTA * (unsigned)t;
                unsigned v;
                do {
                    asm volatile("ld.acquire.gpu.u32 %0, [%1];"
                                 : "=r"(v) : "l"(arr) : "memory");
                } while (v < target);
            }
            __syncthreads();

            // ---- MMA phase ----
            const uint32_t* hfr =
                &g_Hfrag[(t + 1) & 1][(mtg * 32 + kh * 8) * 128 + lane * 4];

            float acc[2][3][4];
#pragma unroll
            for (int p = 0; p < 2; p++)
#pragma unroll
                for (int nt = 0; nt < 3; nt++)
#pragma unroll
                    for (int i = 0; i < 4; i++) acc[p][nt][i] = 0.f;

            uint4 ab[8];
#pragma unroll
            for (int p = 0; p < 8; p++)
                ab[p] = __ldcg((const uint4*)&hfr[p * 128]);

#pragma unroll
            for (int kk = 0; kk < 8; kk++) {
                int ks = kh * 8 + kk;
#pragma unroll
                for (int nt = 0; nt < 3; nt++) {
                    uint2 bb = *(const uint2*)&Bsm[((nt * 32 + ks) * 32 + lane) * 2];
                    hmma(acc[0][nt], ab[kk], bb.x, bb.y);
                }
                if (isHi) {
#pragma unroll
                    for (int nt = 0; nt < 3; nt++) {
                        uint2 bb = *(const uint2*)
                            &Bsm[(((3 + nt) * 32 + ks) * 32 + lane) * 2];
                        hmma(acc[1][nt], ab[kk], bb.x, bb.y);
                    }
                }
            }

            // ---- store D partials (12 slots) ----
            const int npass = isHi ? 2 : 1;
#pragma unroll
            for (int p = 0; p < 2; p++) {
                if (p >= npass) break;
                int slot = isHi ? (p * 4 + kh) : (8 + kh);
#pragma unroll
                for (int nt = 0; nt < 3; nt++) {
                    int col = nt * 8 + tig * 2;
                    int lb  = mtl * 16 + gid;
                    *(float2*)&Dsm[(slot * 32 + lb) * DST + col] =
                        make_float2(acc[p][nt][0], acc[p][nt][1]);
                    *(float2*)&Dsm[(slot * 32 + lb + 8) * DST + col] =
                        make_float2(acc[p][nt][2], acc[p][nt][3]);
                }
            }
            __syncthreads();
        }

        // ---- epilogue: threads 0-255, one (b, j) each ----
        if (tid < 256) {
            float s0 = 0.f, s1 = 0.f, s2 = 0.f;
            if (t > 0) {
#pragma unroll
                for (int sl = 0; sl < NSLOT; sl++) {
                    const float* pr = &Dsm[(sl * 32 + eb) * DST + jl * 3];
                    s0 += pr[0]; s1 += pr[1]; s2 += pr[2];
                }
            }

            float rr = fsig(xr + s0 + bR);
            float zz = fsig(xz + s1 + bZ);
            float nn = ftanh(xn + rr * (s2 + bN));
            float hnew = (1.0f - zz) * nn + zz * hprev;
            hprev = hnew;

            g_HS[(t * B_SZ + b0 + eb) * H_SZ + j0 + jl] = hnew;

            float hlo = bflo(hnew);
            float hn1 = __shfl_down_sync(0xffffffffu, hnew, 1);
            float hl1 = __shfl_down_sync(0xffffffffu, hlo, 1);
            if (!(jl & 1)) {
                uint32_t* hw = g_Hfrag[t & 1];
                int r   = b0 + eb;
                int c   = j0 + jl;
                int ks  = c >> 4;
                int lnw = (r & 7) * 4 + ((c >> 1) & 3);
                int reg = (((c >> 3) & 1) << 1) | ((r >> 3) & 1);
                hw[((r >> 4) * 32 + ks) * 128 + lnw * 4 + reg]       = pkbf(hnew, hn1);
                hw[(((r >> 4) + 4) * 32 + ks) * 128 + lnw * 4 + reg] = pkbf(hlo, hl1);
            }
        }

        __syncthreads();   // all h-frag stores done before release
        if (tid == 0)
            asm volatile("red.release.gpu.add.u32 [%0], %1;"
                         :: "l"(arr), "r"(1u) : "memory");
    }

    // ---- replay-safe per-group counter reset ----
    if (tid == 0) {
        unsigned target = (unsigned)GRPCTA * (unsigned)T_STEPS;
        unsigned v;
        do {
            asm volatile("ld.acquire.gpu.u32 %0, [%1];"
                         : "=r"(v) : "l"(arr) : "memory");
        } while (v < target);
        if (atomicAdd(&g_cnt2[grp][0], 1u) == (unsigned)(GRPCTA - 1)) {
            atomicExch(&g_cnt2[grp][0], 0u);
            atomicExch(&g_arr2[grp][0], 0u);
        }
    }
}

// ---------------------------------------------------------------------------
// K3: y = HS @ w_out^T + b_out   (M=32768, N=16, K=512)
// ---------------------------------------------------------------------------
__global__ void __launch_bounds__(128, 4)
k3_out(const float* __restrict__ wout, const float* __restrict__ bout,
       float* __restrict__ y)
{
    __shared__ float As[32][132];
    __shared__ float Wsh[32][16];

    const int tid = threadIdx.x;
    const int tx = tid & 3;
    const int ty = tid >> 2;
    const int m0 = blockIdx.x * 128;

    float c[4][4];
#pragma unroll
    for (int i = 0; i < 4; i++)
#pragma unroll
        for (int jj = 0; jj < 4; jj++) c[i][jj] = 0.f;

    for (int kc = 0; kc < H_SZ; kc += 32) {
        __syncthreads();
#pragma unroll
        for (int i = 0; i < 8; i++) {
            int lin = tid + i * 128;
            int m = lin >> 3, k4 = lin & 7;
            float4 v = *(const float4*)&g_HS[(m0 + m) * H_SZ + kc + k4 * 4];
            As[k4 * 4 + 0][m] = v.x; As[k4 * 4 + 1][m] = v.y;
            As[k4 * 4 + 2][m] = v.z; As[k4 * 4 + 3][m] = v.w;
        }
#pragma unroll
        for (int i = 0; i < 4; i++) {
            int lin = tid + i * 128;
            int n = lin >> 5, k = lin & 31;
            Wsh[k][n] = wout[n * H_SZ + kc + k];
        }
        __syncthreads();
#pragma unroll
        for (int k = 0; k < 32; k++) {
            float a[4], w[4];
#pragma unroll
            for (int i = 0; i < 4; i++) a[i] = As[k][ty * 4 + i];
#pragma unroll
            for (int jj = 0; jj < 4; jj++) w[jj] = Wsh[k][tx * 4 + jj];
#pragma unroll
            for (int i = 0; i < 4; i++)
#pragma unroll
                for (int jj = 0; jj < 4; jj++)
                    c[i][jj] = fmaf(a[i], w[jj], c[i][jj]);
        }
    }

    float bb[4];
#pragma unroll
    for (int jj = 0; jj < 4; jj++) bb[jj] = __ldg(&bout[tx * 4 + jj]);
#pragma unroll
    for (int i = 0; i < 4; i++) {
        float4 v;
        v.x = c[i][0] + bb[0]; v.y = c[i][1] + bb[1];
        v.z = c[i][2] + bb[2]; v.w = c[i][3] + bb[3];
        *(float4*)&y[(m0 + ty * 4 + i) * O_SZ + tx * 4] = v;
    }
}

// ---------------------------------------------------------------------------
// Entry point
// ---------------------------------------------------------------------------
extern "C" void kernel_launch(void* const* d_in, const int* in_sizes, int n_in,
                              void* d_out, int out_size)
{
    const float* x    = (const float*)d_in[0];   // (T,B,F)
    const float* wih  = (const float*)d_in[1];   // (3H,F)
    const float* whh  = (const float*)d_in[2];   // (3H,H)
    const float* bih  = (const float*)d_in[3];   // (3H)
    const float* bhh  = (const float*)d_in[4];   // (3H)
    const float* wout = (const float*)d_in[5];   // (O,H)
    const float* bout = (const float*)d_in[6];   // (O)
    float* y = (float*)d_out;                    // (T,B,O)

    cudaFuncSetAttribute(k2_gru, cudaFuncAttributeMaxDynamicSharedMemorySize,
                         SMEM2_BYTES);

    // 0) prepack x and w_ih into bf16 hi/lo HMMA fragments
    k0_pack<<<NTILES_A + NTILES_WN, 256>>>(x, wih);

    // 1) xg = x @ w_ih^T + b_ih  (HMMA on prepacked frags)
    k1_xg<<<dim3(G_SZ / 64, NTILES_A / 8), 256>>>(bih);

    // 2) persistent GRU recurrence (HMMA, 16 warps, 2 barrier groups)
    k2_gru<<<NCTA2, NTHR2, SMEM2_BYTES>>>(whh, bhh);

    // 3) output projection
    k3_out<<<(T_STEPS * B_SZ) / 128, 128>>>(wout, bout, y);
}

// round 9
// speedup vs baseline: 1.1532x; 1.1532x over previous
#include <cuda_runtime.h>
#include <cuda_bf16.h>
#include <math.h>
#include <stdint.h>

// Problem constants
#define T_STEPS 512
#define B_SZ    64
#define F_SZ    128
#define H_SZ    512
#define O_SZ    16
#define G_SZ    (3 * H_SZ)   // 1536

// K2 config: 256 CTAs = 4 batch-groups x 64 j-blocks; CTA = 16 batches x 8 j
// 2 CTAs/SM co-resident -> 72 HMMA/SMSP/step.
#define NCTA2   256
#define NTHR2   256
#define JPC     8
#define GRPCTA  64            // CTAs per batch-group
#define NGRP    4

// K2 dynamic SMEM
#define BSM_U32     (2 * 3 * 32 * 32 * 2)   // 12288 u32 = 49152 B
#define DST         26                       // Dsm row stride (floats)
#define NSLOT       8
#define DSM_FLOATS  (NSLOT * 16 * DST)       // 3328
#define SMEM2_BYTES (BSM_U32 * 4 + DSM_FLOATS * 4)   // 62464

// ---------------------------------------------------------------------------
// Device scratch
// ---------------------------------------------------------------------------
__device__ float g_XG[T_STEPS * B_SZ * G_SZ];       // input-side gate preacts
__device__ float g_HS[T_STEPS * B_SZ * H_SZ];       // hidden states (for K3)
// h in HMMA A-fragment layout: [buf][(mt*32 + ks)*128 + lane*4 + reg]
// mt 0-3: h_hi for batch16 groups; mt 4-7: h_lo.
__device__ uint32_t g_Hfrag[2][8 * 32 * 128];
__device__ __align__(128) unsigned g_arr4[NGRP][32];   // per-group arrival counters
__device__ __align__(128) unsigned g_cnt4[NGRP][32];   // per-group reset counters

// ---------------------------------------------------------------------------
// Helpers
// ---------------------------------------------------------------------------
__device__ __forceinline__ float fsig(float x) { return 1.0f / (1.0f + __expf(-x)); }
__device__ __forceinline__ float ftanh(float x) { return 2.0f / (1.0f + __expf(-2.0f * x)) - 1.0f; }

__device__ __forceinline__ uint32_t pkbf(float a, float b) {
    return (uint32_t)__bfloat16_as_ushort(__float2bfloat16(a))
         | ((uint32_t)__bfloat16_as_ushort(__float2bfloat16(b)) << 16);
}
__device__ __forceinline__ float bflo(float v) {
    return v - __bfloat162float(__float2bfloat16(v));
}

// mma.sync m16n8k16 row.col f32.bf16.bf16.f32
__device__ __forceinline__ void hmma(float* d, const uint4& a, uint32_t b0, uint32_t b1) {
    asm volatile(
        "mma.sync.aligned.m16n8k16.row.col.f32.bf16.bf16.f32 "
        "{%0,%1,%2,%3}, {%4,%5,%6,%7}, {%8,%9}, {%0,%1,%2,%3};"
        : "+f"(d[0]), "+f"(d[1]), "+f"(d[2]), "+f"(d[3])
        : "r"(a.x), "r"(a.y), "r"(a.z), "r"(a.w), "r"(b0), "r"(b1));
}

// ---------------------------------------------------------------------------
// K1: xg = x @ w_ih^T + b_ih  via HMMA split-bf16 (3 products). (R7 version)
// ---------------------------------------------------------------------------
__global__ void __launch_bounds__(256, 2)
k1_xg(const float* __restrict__ x, const float* __restrict__ wih,
      const float* __restrict__ bih)
{
    __shared__ uint32_t Bf[2][8][8][32][2];

    const int tid  = threadIdx.x;
    const int wid  = tid >> 5;
    const int lane = tid & 31;
    const int m0 = blockIdx.y * 128;
    const int n0 = blockIdx.x * 64;

    for (int idx = tid; idx < 2 * 8 * 8 * 32; idx += 256) {
        int el = idx & 31;
        int ks = (idx >> 5) & 7;
        int nt = (idx >> 8) & 7;
        int p  = idx >> 11;
        const float* wr = &wih[(n0 + nt * 8 + (el >> 2)) * F_SZ + ks * 16 + (el & 3) * 2];
        float w00 = wr[0], w01 = wr[1], w10 = wr[8], w11 = wr[9];
        if (p) { w00 = bflo(w00); w01 = bflo(w01); w10 = bflo(w10); w11 = bflo(w11); }
        Bf[p][nt][ks][el][0] = pkbf(w00, w01);
        Bf[p][nt][ks][el][1] = pkbf(w10, w11);
    }
    __syncthreads();

    const int mt  = wid;
    const int gid = lane >> 2;
    const int tig = lane & 3;
    const float* xr0 = &x[(m0 + mt * 16 + gid) * F_SZ];
    const float* xr1 = xr0 + 8 * F_SZ;

    float acc[8][4];
#pragma unroll
    for (int nt = 0; nt < 8; nt++)
#pragma unroll
        for (int i = 0; i < 4; i++) acc[nt][i] = 0.f;

#pragma unroll
    for (int ks = 0; ks < 8; ks++) {
        int kc = ks * 16 + tig * 2;
        float2 x00 = *(const float2*)&xr0[kc];
        float2 x10 = *(const float2*)&xr1[kc];
        float2 x01 = *(const float2*)&xr0[kc + 8];
        float2 x11 = *(const float2*)&xr1[kc + 8];
        uint4 ahi = make_uint4(pkbf(x00.x, x00.y), pkbf(x10.x, x10.y),
                               pkbf(x01.x, x01.y), pkbf(x11.x, x11.y));
        uint4 alo = make_uint4(pkbf(bflo(x00.x), bflo(x00.y)),
                               pkbf(bflo(x10.x), bflo(x10.y)),
                               pkbf(bflo(x01.x), bflo(x01.y)),
                               pkbf(bflo(x11.x), bflo(x11.y)));
#pragma unroll
        for (int nt = 0; nt < 8; nt++) {
            uint2 bh = *(const uint2*)&Bf[0][nt][ks][lane][0];
            uint2 bl = *(const uint2*)&Bf[1][nt][ks][lane][0];
            hmma(acc[nt], ahi, bh.x, bh.y);
            hmma(acc[nt], alo, bh.x, bh.y);
            hmma(acc[nt], ahi, bl.x, bl.y);
        }
    }

    const int row0 = m0 + mt * 16 + gid;
#pragma unroll
    for (int nt = 0; nt < 8; nt++) {
        int col = n0 + nt * 8 + tig * 2;
        float2 bb = *(const float2*)&bih[col];
        *(float2*)&g_XG[row0 * G_SZ + col] =
            make_float2(acc[nt][0] + bb.x, acc[nt][1] + bb.y);
        *(float2*)&g_XG[(row0 + 8) * G_SZ + col] =
            make_float2(acc[nt][2] + bb.x, acc[nt][3] + bb.y);
    }
}

// ---------------------------------------------------------------------------
// K2: persistent HMMA GRU recurrence, 256 CTAs (16 batches x 8 j each).
// All warps identical: warp w owns ks in [4w, 4w+4), all 3 split-products
// accumulated into one 16x24 D tile (rows = own 16 batches).
// ---------------------------------------------------------------------------
__global__ void __launch_bounds__(NTHR2, 2)
k2_gru(const float* __restrict__ wHH, const float* __restrict__ bHH)
{
    extern __shared__ uint32_t sm[];
    uint32_t* Bsm = sm;
    float*    Dsm = (float*)(sm + BSM_U32);

    const int tid  = threadIdx.x;
    const int wid  = tid >> 5;
    const int lane = tid & 31;
    const int bid  = blockIdx.x;
    const int grp  = bid & 3;
    const int b0   = grp * 16;
    const int j0   = (bid >> 2) * JPC;

    // ---- one-time: W -> bf16 hi/lo fragments in SMEM (24 real cols) ----
    for (int idx = tid; idx < 2 * 3 * 32 * 32; idx += NTHR2) {
        int el = idx & 31;
        int ks = (idx >> 5) & 31;
        int nt = (idx >> 10) % 3;
        int p  = idx / (3 * 1024);
        int n  = nt * 8 + (el >> 2);
        int jl = n / 3, g = n % 3;
        const float* wr = &wHH[(g * H_SZ + j0 + jl) * H_SZ + ks * 16 + (el & 3) * 2];
        float w00 = wr[0], w01 = wr[1], w10 = wr[8], w11 = wr[9];
        if (p) { w00 = bflo(w00); w01 = bflo(w01); w10 = bflo(w10); w11 = bflo(w11); }
        int base = ((((p * 3 + nt) * 32) + ks) * 32 + el) * 2;
        Bsm[base    ] = pkbf(w00, w01);
        Bsm[base + 1] = pkbf(w10, w11);
    }

    // ---- epilogue state: threads 0-127 = (batch eb 0..15, j-local jl 0..7) ----
    const int eb = tid >> 3;       // valid for tid < 128
    const int jl = tid & 7;
    float bR = 0.f, bZ = 0.f, bN = 0.f, hprev = 0.f;
    if (tid < 128) {
        bR = __ldg(&bHH[0 * H_SZ + j0 + jl]);
        bZ = __ldg(&bHH[1 * H_SZ + j0 + jl]);
        bN = __ldg(&bHH[2 * H_SZ + j0 + jl]);
    }
    __syncthreads();

    // ---- MMA warp constants ----
    const int ks0 = wid * 4;
    const int gid = lane >> 2;
    const int tig = lane & 3;

    unsigned* arr = &g_arr4[grp][0];

    for (int t = 0; t < T_STEPS; t++) {
        // prefetch xg (independent of h)
        float xr = 0.f, xz = 0.f, xn = 0.f;
        if (tid < 128) {
            const int gbase = (t * B_SZ + b0 + eb) * G_SZ + j0 + jl;
            xr = __ldg(&g_XG[gbase]);
            xz = __ldg(&g_XG[gbase + H_SZ]);
            xn = __ldg(&g_XG[gbase + 2 * H_SZ]);
        }

        if (t > 0) {
            // ---- group barrier: all 64 CTAs of this batch-quarter committed ----
            if (tid == 0) {
                unsigned target = (unsigned)GRPCTA * (unsigned)t;
                unsigned v;
                do {
                    asm volatile("ld.acquire.gpu.u32 %0, [%1];"
                                 : "=r"(v) : "l"(arr) : "memory");
                } while (v < target);
            }
            __syncthreads();

            // ---- MMA phase: all 8 warps, 36 HMMA each ----
            const uint32_t* hb = g_Hfrag[(t + 1) & 1];
            const uint32_t* hhi = &hb[(grp * 32 + ks0) * 128 + lane * 4];
            const uint32_t* hlo = &hb[((4 + grp) * 32 + ks0) * 128 + lane * 4];

            uint4 ahi[4], alo[4];
#pragma unroll
            for (int kk = 0; kk < 4; kk++) {
                ahi[kk] = __ldcg((const uint4*)&hhi[kk * 128]);
                alo[kk] = __ldcg((const uint4*)&hlo[kk * 128]);
            }

            float acc[3][4];
#pragma unroll
            for (int nt = 0; nt < 3; nt++)
#pragma unroll
                for (int i = 0; i < 4; i++) acc[nt][i] = 0.f;

#pragma unroll
            for (int kk = 0; kk < 4; kk++) {
                int ks = ks0 + kk;
#pragma unroll
                for (int nt = 0; nt < 3; nt++) {
                    uint2 bh = *(const uint2*)&Bsm[((nt * 32 + ks) * 32 + lane) * 2];
                    uint2 bl = *(const uint2*)&Bsm[(((3 + nt) * 32 + ks) * 32 + lane) * 2];
                    hmma(acc[nt], ahi[kk], bh.x, bh.y);   // hi . W_hi
                    hmma(acc[nt], alo[kk], bh.x, bh.y);   // lo . W_hi
                    hmma(acc[nt], ahi[kk], bl.x, bl.y);   // hi . W_lo
                }
            }

            // ---- store D partials (slot = warp, 16 rows each) ----
#pragma unroll
            for (int nt = 0; nt < 3; nt++) {
                int col = nt * 8 + tig * 2;
                *(float2*)&Dsm[(wid * 16 + gid) * DST + col] =
                    make_float2(acc[nt][0], acc[nt][1]);
                *(float2*)&Dsm[(wid * 16 + gid + 8) * DST + col] =
                    make_float2(acc[nt][2], acc[nt][3]);
            }
            __syncthreads();
        }

        // ---- epilogue: threads 0-127, one (b, j) each ----
        if (tid < 128) {
            float s0 = 0.f, s1 = 0.f, s2 = 0.f;
            if (t > 0) {
#pragma unroll
                for (int sl = 0; sl < NSLOT; sl++) {
                    const float* pr = &Dsm[(sl * 16 + eb) * DST + jl * 3];
                    s0 += pr[0]; s1 += pr[1]; s2 += pr[2];
                }
            }

            float rr = fsig(xr + s0 + bR);
            float zz = fsig(xz + s1 + bZ);
            float nn = ftanh(xn + rr * (s2 + bN));
            float hnew = (1.0f - zz) * nn + zz * hprev;
            hprev = hnew;

            g_HS[(t * B_SZ + b0 + eb) * H_SZ + j0 + jl] = hnew;

            float hlo2 = bflo(hnew);
            float hn1 = __shfl_down_sync(0xffffffffu, hnew, 1);
            float hl1 = __shfl_down_sync(0xffffffffu, hlo2, 1);
            if (!(jl & 1)) {
                uint32_t* hw = g_Hfrag[t & 1];
                int r   = b0 + eb;
                int c   = j0 + jl;
                int ks  = c >> 4;
                int lnw = (r & 7) * 4 + ((c >> 1) & 3);
                int reg = (((c >> 3) & 1) << 1) | ((r >> 3) & 1);
                hw[((r >> 4) * 32 + ks) * 128 + lnw * 4 + reg]       = pkbf(hnew, hn1);
                hw[(((r >> 4) + 4) * 32 + ks) * 128 + lnw * 4 + reg] = pkbf(hlo2, hl1);
            }
        }

        __syncthreads();   // all h-frag stores done before release
        if (tid == 0)
            asm volatile("red.release.gpu.add.u32 [%0], %1;"
                         :: "l"(arr), "r"(1u) : "memory");
    }

    // ---- replay-safe per-group counter reset ----
    if (tid == 0) {
        unsigned target = (unsigned)GRPCTA * (unsigned)T_STEPS;
        unsigned v;
        do {
            asm volatile("ld.acquire.gpu.u32 %0, [%1];"
                         : "=r"(v) : "l"(arr) : "memory");
        } while (v < target);
        if (atomicAdd(&g_cnt4[grp][0], 1u) == (unsigned)(GRPCTA - 1)) {
            atomicExch(&g_cnt4[grp][0], 0u);
            atomicExch(&g_arr4[grp][0], 0u);
        }
    }
}

// ---------------------------------------------------------------------------
// K3: y = HS @ w_out^T + b_out   (M=32768, N=16, K=512)
// ---------------------------------------------------------------------------
__global__ void __launch_bounds__(128, 4)
k3_out(const float* __restrict__ wout, const float* __restrict__ bout,
       float* __restrict__ y)
{
    __shared__ float As[32][132];
    __shared__ float Wsh[32][16];

    const int tid = threadIdx.x;
    const int tx = tid & 3;
    const int ty = tid >> 2;
    const int m0 = blockIdx.x * 128;

    float c[4][4];
#pragma unroll
    for (int i = 0; i < 4; i++)
#pragma unroll
        for (int jj = 0; jj < 4; jj++) c[i][jj] = 0.f;

    for (int kc = 0; kc < H_SZ; kc += 32) {
        __syncthreads();
#pragma unroll
        for (int i = 0; i < 8; i++) {
            int lin = tid + i * 128;
            int m = lin >> 3, k4 = lin & 7;
            float4 v = *(const float4*)&g_HS[(m0 + m) * H_SZ + kc + k4 * 4];
            As[k4 * 4 + 0][m] = v.x; As[k4 * 4 + 1][m] = v.y;
            As[k4 * 4 + 2][m] = v.z; As[k4 * 4 + 3][m] = v.w;
        }
#pragma unroll
        for (int i = 0; i < 4; i++) {
            int lin = tid + i * 128;
            int n = lin >> 5, k = lin & 31;
            Wsh[k][n] = wout[n * H_SZ + kc + k];
        }
        __syncthreads();
#pragma unroll
        for (int k = 0; k < 32; k++) {
            float a[4], w[4];
#pragma unroll
            for (int i = 0; i < 4; i++) a[i] = As[k][ty * 4 + i];
#pragma unroll
            for (int jj = 0; jj < 4; jj++) w[jj] = Wsh[k][tx * 4 + jj];
#pragma unroll
            for (int i = 0; i < 4; i++)
#pragma unroll
                for (int jj = 0; jj < 4; jj++)
                    c[i][jj] = fmaf(a[i], w[jj], c[i][jj]);
        }
    }

    float bb[4];
#pragma unroll
    for (int jj = 0; jj < 4; jj++) bb[jj] = __ldg(&bout[tx * 4 + jj]);
#pragma unroll
    for (int i = 0; i < 4; i++) {
        float4 v;
        v.x = c[i][0] + bb[0]; v.y = c[i][1] + bb[1];
        v.z = c[i][2] + bb[2]; v.w = c[i][3] + bb[3];
        *(float4*)&y[(m0 + ty * 4 + i) * O_SZ + tx * 4] = v;
    }
}

// ---------------------------------------------------------------------------
// Entry point
// ---------------------------------------------------------------------------
extern "C" void kernel_launch(void* const* d_in, const int* in_sizes, int n_in,
                              void* d_out, int out_size)
{
    const float* x    = (const float*)d_in[0];   // (T,B,F)
    const float* wih  = (const float*)d_in[1];   // (3H,F)
    const float* whh  = (const float*)d_in[2];   // (3H,H)
    const float* bih  = (const float*)d_in[3];   // (3H)
    const float* bhh  = (const float*)d_in[4];   // (3H)
    const float* wout = (const float*)d_in[5];   // (O,H)
    const float* bout = (const float*)d_in[6];   // (O)
    float* y = (float*)d_out;                    // (T,B,O)

    cudaFuncSetAttribute(k2_gru, cudaFuncAttributeMaxDynamicSharedMemorySize,
                         SMEM2_BYTES);

    // 1) xg = x @ w_ih^T + b_ih  (HMMA split-bf16)
    k1_xg<<<dim3(G_SZ / 64, (T_STEPS * B_SZ) / 128), 256>>>(x, wih, bih);

    // 2) persistent GRU recurrence (HMMA, 256 CTAs, 4 barrier groups)
    k2_gru<<<NCTA2, NTHR2, SMEM2_BYTES>>>(whh, bhh);

    // 3) output projection
    k3_out<<<(T_STEPS * B_SZ) / 128, 128>>>(wout, bout, y);
}

// round 10
// speedup vs baseline: 1.2442x; 1.0789x over previous
#include <cuda_runtime.h>
#include <cuda_bf16.h>
#include <math.h>
#include <stdint.h>

// Problem constants
#define T_STEPS 512
#define B_SZ    64
#define F_SZ    128
#define H_SZ    512
#define O_SZ    16
#define G_SZ    (3 * H_SZ)   // 1536

// K2 config: 256 CTAs = 4 batch-groups x 64 j-blocks; CTA = 16 batches x 8 j
#define NCTA2   256
#define NTHR2   256
#define JPC     8
#define GRPCTA  64            // CTAs per batch-group
#define NGRP    4

// K2 dynamic SMEM
#define BSM_U32     (2 * 3 * 32 * 32 * 2)   // 12288 u32 = 49152 B
#define DST         26                       // Dsm row stride (floats)
#define NSLOT       8
#define DSM_FLOATS  (NSLOT * 16 * DST)       // 3328
#define SMEM2_BYTES (BSM_U32 * 4 + DSM_FLOATS * 4)   // 62464

// ---------------------------------------------------------------------------
// Device scratch
// ---------------------------------------------------------------------------
__device__ float g_XG[T_STEPS * B_SZ * G_SZ];       // input-side gate preacts
__device__ float g_HS[T_STEPS * B_SZ * H_SZ];       // hidden states (for K3)
// h_hi (bf16) in HMMA A-fragment layout: [buf][(grp*32 + ks)*128 + lane*4 + reg]
__device__ uint32_t g_Hfrag[2][4 * 32 * 128];
__device__ __align__(128) unsigned g_arr4[NGRP][32];   // per-group arrival counters
__device__ __align__(128) unsigned g_cnt4[NGRP][32];   // per-group reset counters

// ---------------------------------------------------------------------------
// Helpers
// ---------------------------------------------------------------------------
__device__ __forceinline__ float fsig(float x) { return 1.0f / (1.0f + __expf(-x)); }
__device__ __forceinline__ float ftanh(float x) { return 2.0f / (1.0f + __expf(-2.0f * x)) - 1.0f; }

__device__ __forceinline__ uint32_t pkbf(float a, float b) {
    return (uint32_t)__bfloat16_as_ushort(__float2bfloat16(a))
         | ((uint32_t)__bfloat16_as_ushort(__float2bfloat16(b)) << 16);
}
__device__ __forceinline__ float bflo(float v) {
    return v - __bfloat162float(__float2bfloat16(v));
}

// mma.sync m16n8k16 row.col f32.bf16.bf16.f32
__device__ __forceinline__ void hmma(float* d, const uint4& a, uint32_t b0, uint32_t b1) {
    asm volatile(
        "mma.sync.aligned.m16n8k16.row.col.f32.bf16.bf16.f32 "
        "{%0,%1,%2,%3}, {%4,%5,%6,%7}, {%8,%9}, {%0,%1,%2,%3};"
        : "+f"(d[0]), "+f"(d[1]), "+f"(d[2]), "+f"(d[3])
        : "r"(a.x), "r"(a.y), "r"(a.z), "r"(a.w), "r"(b0), "r"(b1));
}

// ---------------------------------------------------------------------------
// K1: xg = x @ w_ih^T + b_ih  via HMMA split-bf16 (3 products, full accuracy).
// ---------------------------------------------------------------------------
__global__ void __launch_bounds__(256, 2)
k1_xg(const float* __restrict__ x, const float* __restrict__ wih,
      const float* __restrict__ bih)
{
    __shared__ uint32_t Bf[2][8][8][32][2];

    const int tid  = threadIdx.x;
    const int wid  = tid >> 5;
    const int lane = tid & 31;
    const int m0 = blockIdx.y * 128;
    const int n0 = blockIdx.x * 64;

    for (int idx = tid; idx < 2 * 8 * 8 * 32; idx += 256) {
        int el = idx & 31;
        int ks = (idx >> 5) & 7;
        int nt = (idx >> 8) & 7;
        int p  = idx >> 11;
        const float* wr = &wih[(n0 + nt * 8 + (el >> 2)) * F_SZ + ks * 16 + (el & 3) * 2];
        float w00 = wr[0], w01 = wr[1], w10 = wr[8], w11 = wr[9];
        if (p) { w00 = bflo(w00); w01 = bflo(w01); w10 = bflo(w10); w11 = bflo(w11); }
        Bf[p][nt][ks][el][0] = pkbf(w00, w01);
        Bf[p][nt][ks][el][1] = pkbf(w10, w11);
    }
    __syncthreads();

    const int mt  = wid;
    const int gid = lane >> 2;
    const int tig = lane & 3;
    const float* xr0 = &x[(m0 + mt * 16 + gid) * F_SZ];
    const float* xr1 = xr0 + 8 * F_SZ;

    float acc[8][4];
#pragma unroll
    for (int nt = 0; nt < 8; nt++)
#pragma unroll
        for (int i = 0; i < 4; i++) acc[nt][i] = 0.f;

#pragma unroll
    for (int ks = 0; ks < 8; ks++) {
        int kc = ks * 16 + tig * 2;
        float2 x00 = *(const float2*)&xr0[kc];
        float2 x10 = *(const float2*)&xr1[kc];
        float2 x01 = *(const float2*)&xr0[kc + 8];
        float2 x11 = *(const float2*)&xr1[kc + 8];
        uint4 ahi = make_uint4(pkbf(x00.x, x00.y), pkbf(x10.x, x10.y),
                               pkbf(x01.x, x01.y), pkbf(x11.x, x11.y));
        uint4 alo = make_uint4(pkbf(bflo(x00.x), bflo(x00.y)),
                               pkbf(bflo(x10.x), bflo(x10.y)),
                               pkbf(bflo(x01.x), bflo(x01.y)),
                               pkbf(bflo(x11.x), bflo(x11.y)));
#pragma unroll
        for (int nt = 0; nt < 8; nt++) {
            uint2 bh = *(const uint2*)&Bf[0][nt][ks][lane][0];
            uint2 bl = *(const uint2*)&Bf[1][nt][ks][lane][0];
            hmma(acc[nt], ahi, bh.x, bh.y);
            hmma(acc[nt], alo, bh.x, bh.y);
            hmma(acc[nt], ahi, bl.x, bl.y);
        }
    }

    const int row0 = m0 + mt * 16 + gid;
#pragma unroll
    for (int nt = 0; nt < 8; nt++) {
        int col = n0 + nt * 8 + tig * 2;
        float2 bb = *(const float2*)&bih[col];
        *(float2*)&g_XG[row0 * G_SZ + col] =
            make_float2(acc[nt][0] + bb.x, acc[nt][1] + bb.y);
        *(float2*)&g_XG[(row0 + 8) * G_SZ + col] =
            make_float2(acc[nt][2] + bb.x, acc[nt][3] + bb.y);
    }
}

// ---------------------------------------------------------------------------
// K2: persistent HMMA GRU recurrence, 256 CTAs (16 batches x 8 j each).
// hg = h_hi . (W_hi + W_lo): 2 products into one accumulator, h_lo dropped
// (error ~2^-9 on h only; z*h_prev path stays fp32).
// Warp w owns ks in [4w, 4w+4): 24 HMMA per warp.
// ---------------------------------------------------------------------------
__global__ void __launch_bounds__(NTHR2, 2)
k2_gru(const float* __restrict__ wHH, const float* __restrict__ bHH)
{
    extern __shared__ uint32_t sm[];
    uint32_t* Bsm = sm;
    float*    Dsm = (float*)(sm + BSM_U32);

    const int tid  = threadIdx.x;
    const int wid  = tid >> 5;
    const int lane = tid & 31;
    const int bid  = blockIdx.x;
    const int grp  = bid & 3;
    const int b0   = grp * 16;
    const int j0   = (bid >> 2) * JPC;

    // ---- one-time: W -> bf16 hi/lo fragments in SMEM (24 real cols) ----
    for (int idx = tid; idx < 2 * 3 * 32 * 32; idx += NTHR2) {
        int el = idx & 31;
        int ks = (idx >> 5) & 31;
        int nt = (idx >> 10) % 3;
        int p  = idx / (3 * 1024);
        int n  = nt * 8 + (el >> 2);
        int jl = n / 3, g = n % 3;
        const float* wr = &wHH[(g * H_SZ + j0 + jl) * H_SZ + ks * 16 + (el & 3) * 2];
        float w00 = wr[0], w01 = wr[1], w10 = wr[8], w11 = wr[9];
        if (p) { w00 = bflo(w00); w01 = bflo(w01); w10 = bflo(w10); w11 = bflo(w11); }
        int base = ((((p * 3 + nt) * 32) + ks) * 32 + el) * 2;
        Bsm[base    ] = pkbf(w00, w01);
        Bsm[base + 1] = pkbf(w10, w11);
    }

    // ---- epilogue state: threads 0-127 = (batch eb 0..15, j-local jl 0..7) ----
    const int eb = tid >> 3;       // valid for tid < 128
    const int jl = tid & 7;
    float bR = 0.f, bZ = 0.f, bN = 0.f, hprev = 0.f;
    if (tid < 128) {
        bR = __ldg(&bHH[0 * H_SZ + j0 + jl]);
        bZ = __ldg(&bHH[1 * H_SZ + j0 + jl]);
        bN = __ldg(&bHH[2 * H_SZ + j0 + jl]);
    }
    __syncthreads();

    // ---- MMA warp constants ----
    const int ks0 = wid * 4;
    const int gid = lane >> 2;
    const int tig = lane & 3;

    unsigned* arr = &g_arr4[grp][0];

    for (int t = 0; t < T_STEPS; t++) {
        // prefetch xg (independent of h)
        float xr = 0.f, xz = 0.f, xn = 0.f;
        if (tid < 128) {
            const int gbase = (t * B_SZ + b0 + eb) * G_SZ + j0 + jl;
            xr = __ldg(&g_XG[gbase]);
            xz = __ldg(&g_XG[gbase + H_SZ]);
            xn = __ldg(&g_XG[gbase + 2 * H_SZ]);
        }

        if (t > 0) {
            // ---- group barrier: all 64 CTAs of this batch-quarter committed ----
            if (tid == 0) {
                unsigned target = (unsigned)GRPCTA * (unsigned)t;
                unsigned v;
                do {
                    asm volatile("ld.acquire.gpu.u32 %0, [%1];"
                                 : "=r"(v) : "l"(arr) : "memory");
                } while (v < target);
            }
            __syncthreads();

            // ---- MMA phase: 8 warps, 24 HMMA each ----
            const uint32_t* hhi =
                &g_Hfrag[(t + 1) & 1][(grp * 32 + ks0) * 128 + lane * 4];

            uint4 ahi[4];
#pragma unroll
            for (int kk = 0; kk < 4; kk++)
                ahi[kk] = __ldcg((const uint4*)&hhi[kk * 128]);

            float acc[3][4];
#pragma unroll
            for (int nt = 0; nt < 3; nt++)
#pragma unroll
                for (int i = 0; i < 4; i++) acc[nt][i] = 0.f;

#pragma unroll
            for (int kk = 0; kk < 4; kk++) {
                int ks = ks0 + kk;
#pragma unroll
                for (int nt = 0; nt < 3; nt++) {
                    uint2 bh = *(const uint2*)&Bsm[((nt * 32 + ks) * 32 + lane) * 2];
                    uint2 bl = *(const uint2*)&Bsm[(((3 + nt) * 32 + ks) * 32 + lane) * 2];
                    hmma(acc[nt], ahi[kk], bh.x, bh.y);   // h_hi . W_hi
                    hmma(acc[nt], ahi[kk], bl.x, bl.y);   // h_hi . W_lo
                }
            }

            // ---- store D partials (slot = warp, 16 rows each) ----
#pragma unroll
            for (int nt = 0; nt < 3; nt++) {
                int col = nt * 8 + tig * 2;
                *(float2*)&Dsm[(wid * 16 + gid) * DST + col] =
                    make_float2(acc[nt][0], acc[nt][1]);
                *(float2*)&Dsm[(wid * 16 + gid + 8) * DST + col] =
                    make_float2(acc[nt][2], acc[nt][3]);
            }
            __syncthreads();
        }

        // ---- epilogue: threads 0-127, one (b, j) each ----
        if (tid < 128) {
            float s0 = 0.f, s1 = 0.f, s2 = 0.f;
            if (t > 0) {
#pragma unroll
                for (int sl = 0; sl < NSLOT; sl++) {
                    const float* pr = &Dsm[(sl * 16 + eb) * DST + jl * 3];
                    s0 += pr[0]; s1 += pr[1]; s2 += pr[2];
                }
            }

            float rr = fsig(xr + s0 + bR);
            float zz = fsig(xz + s1 + bZ);
            float nn = ftanh(xn + rr * (s2 + bN));
            float hnew = (1.0f - zz) * nn + zz * hprev;
            hprev = hnew;

            // h_hi fragment store (only hi part needed now)
            float hn1 = __shfl_down_sync(0xffffffffu, hnew, 1);
            if (!(jl & 1)) {
                uint32_t* hw = g_Hfrag[t & 1];
                int r   = b0 + eb;
                int c   = j0 + jl;
                int ks  = c >> 4;
                int lnw = (r & 7) * 4 + ((c >> 1) & 3);
                int reg = (((c >> 3) & 1) << 1) | ((r >> 3) & 1);
                hw[((r >> 4) * 32 + ks) * 128 + lnw * 4 + reg] = pkbf(hnew, hn1);
            }

            g_HS[(t * B_SZ + b0 + eb) * H_SZ + j0 + jl] = hnew;
        }

        __syncthreads();   // all h-frag stores done before release
        if (tid == 0)
            asm volatile("red.release.gpu.add.u32 [%0], %1;"
                         :: "l"(arr), "r"(1u) : "memory");
    }

    // ---- replay-safe per-group counter reset ----
    if (tid == 0) {
        unsigned target = (unsigned)GRPCTA * (unsigned)T_STEPS;
        unsigned v;
        do {
            asm volatile("ld.acquire.gpu.u32 %0, [%1];"
                         : "=r"(v) : "l"(arr) : "memory");
        } while (v < target);
        if (atomicAdd(&g_cnt4[grp][0], 1u) == (unsigned)(GRPCTA - 1)) {
            atomicExch(&g_cnt4[grp][0], 0u);
            atomicExch(&g_arr4[grp][0], 0u);
        }
    }
}

// ---------------------------------------------------------------------------
// K3: y = HS @ w_out^T + b_out   (M=32768, N=16, K=512)
// ---------------------------------------------------------------------------
__global__ void __launch_bounds__(128, 4)
k3_out(const float* __restrict__ wout, const float* __restrict__ bout,
       float* __restrict__ y)
{
    __shared__ float As[32][132];
    __shared__ float Wsh[32][16];

    const int tid = threadIdx.x;
    const int tx = tid & 3;
    const int ty = tid >> 2;
    const int m0 = blockIdx.x * 128;

    float c[4][4];
#pragma unroll
    for (int i = 0; i < 4; i++)
#pragma unroll
        for (int jj = 0; jj < 4; jj++) c[i][jj] = 0.f;

    for (int kc = 0; kc < H_SZ; kc += 32) {
        __syncthreads();
#pragma unroll
        for (int i = 0; i < 8; i++) {
            int lin = tid + i * 128;
            int m = lin >> 3, k4 = lin & 7;
            float4 v = *(const float4*)&g_HS[(m0 + m) * H_SZ + kc + k4 * 4];
            As[k4 * 4 + 0][m] = v.x; As[k4 * 4 + 1][m] = v.y;
            As[k4 * 4 + 2][m] = v.z; As[k4 * 4 + 3][m] = v.w;
        }
#pragma unroll
        for (int i = 0; i < 4; i++) {
            int lin = tid + i * 128;
            int n = lin >> 5, k = lin & 31;
            Wsh[k][n] = wout[n * H_SZ + kc + k];
        }
        __syncthreads();
#pragma unroll
        for (int k = 0; k < 32; k++) {
            float a[4], w[4];
#pragma unroll
            for (int i = 0; i < 4; i++) a[i] = As[k][ty * 4 + i];
#pragma unroll
            for (int jj = 0; jj < 4; jj++) w[jj] = Wsh[k][tx * 4 + jj];
#pragma unroll
            for (int i = 0; i < 4; i++)
#pragma unroll
                for (int jj = 0; jj < 4; jj++)
                    c[i][jj] = fmaf(a[i], w[jj], c[i][jj]);
        }
    }

    float bb[4];
#pragma unroll
    for (int jj = 0; jj < 4; jj++) bb[jj] = __ldg(&bout[tx * 4 + jj]);
#pragma unroll
    for (int i = 0; i < 4; i++) {
        float4 v;
        v.x = c[i][0] + bb[0]; v.y = c[i][1] + bb[1];
        v.z = c[i][2] + bb[2]; v.w = c[i][3] + bb[3];
        *(float4*)&y[(m0 + ty * 4 + i) * O_SZ + tx * 4] = v;
    }
}

// ---------------------------------------------------------------------------
// Entry point
// ---------------------------------------------------------------------------
extern "C" void kernel_launch(void* const* d_in, const int* in_sizes, int n_in,
                              void* d_out, int out_size)
{
    const float* x    = (const float*)d_in[0];   // (T,B,F)
    const float* wih  = (const float*)d_in[1];   // (3H,F)
    const float* whh  = (const float*)d_in[2];   // (3H,H)
    const float* bih  = (const float*)d_in[3];   // (3H)
    const float* bhh  = (const float*)d_in[4];   // (3H)
    const float* wout = (const float*)d_in[5];   // (O,H)
    const float* bout = (const float*)d_in[6];   // (O)
    float* y = (float*)d_out;                    // (T,B,O)

    cudaFuncSetAttribute(k2_gru, cudaFuncAttributeMaxDynamicSharedMemorySize,
                         SMEM2_BYTES);

    // 1) xg = x @ w_ih^T + b_ih  (HMMA split-bf16, 3 products)
    k1_xg<<<dim3(G_SZ / 64, (T_STEPS * B_SZ) / 128), 256>>>(x, wih, bih);

    // 2) persistent GRU recurrence (HMMA, 256 CTAs, 2-product split)
    k2_gru<<<NCTA2, NTHR2, SMEM2_BYTES>>>(whh, bhh);

    // 3) output projection
    k3_out<<<(T_STEPS * B_SZ) / 128, 128>>>(wout, bout, y);
}

// round 11
// speedup vs baseline: 1.3055x; 1.0493x over previous
#include <cuda_runtime.h>
#include <cuda_bf16.h>
#include <cuda_fp16.h>
#include <math.h>
#include <stdint.h>

// Problem constants
#define T_STEPS 512
#define B_SZ    64
#define F_SZ    128
#define H_SZ    512
#define O_SZ    16
#define G_SZ    (3 * H_SZ)   // 1536

// K2 config: 256 CTAs = 4 batch-groups x 64 j-blocks; CTA = 16 batches x 8 j
#define NCTA2   256
#define NTHR2   256
#define JPC     8
#define GRPCTA  64            // CTAs per batch-group
#define NGRP    4

// K2 dynamic SMEM: W fp16 fragments + D exchange
#define BSM_U32     (3 * 32 * 32 * 2)        // 6144 u32 = 24576 B
#define DST         26                       // Dsm row stride (floats)
#define NSLOT       8
#define DSM_FLOATS  (NSLOT * 16 * DST)       // 3328
#define SMEM2_BYTES (BSM_U32 * 4 + DSM_FLOATS * 4)   // 37888

// ---------------------------------------------------------------------------
// Device scratch
// ---------------------------------------------------------------------------
__device__ float g_XG[T_STEPS * B_SZ * G_SZ];       // input-side gate preacts
__device__ float g_HS[T_STEPS * B_SZ * H_SZ];       // hidden states (for K3)
// h (fp16) in HMMA A-fragment layout: [buf][(grp*32 + ks)*128 + lane*4 + reg]
__device__ uint32_t g_Hfrag[2][4 * 32 * 128];
__device__ __align__(128) unsigned g_arr4[NGRP][32];   // per-group arrival counters
__device__ __align__(128) unsigned g_cnt4[NGRP][32];   // per-group reset counters

// ---------------------------------------------------------------------------
// Helpers
// ---------------------------------------------------------------------------
__device__ __forceinline__ float fsig(float x) { return 1.0f / (1.0f + __expf(-x)); }
__device__ __forceinline__ float ftanh(float x) { return 2.0f / (1.0f + __expf(-2.0f * x)) - 1.0f; }

__device__ __forceinline__ uint32_t pkbf(float a, float b) {
    return (uint32_t)__bfloat16_as_ushort(__float2bfloat16(a))
         | ((uint32_t)__bfloat16_as_ushort(__float2bfloat16(b)) << 16);
}
__device__ __forceinline__ float bflo(float v) {
    return v - __bfloat162float(__float2bfloat16(v));
}
__device__ __forceinline__ uint32_t pkhf(float a, float b) {
    __half2 h = __floats2half2_rn(a, b);
    return *(uint32_t*)&h;
}

// mma.sync m16n8k16 row.col f32.bf16.bf16.f32
__device__ __forceinline__ void hmma(float* d, const uint4& a, uint32_t b0, uint32_t b1) {
    asm volatile(
        "mma.sync.aligned.m16n8k16.row.col.f32.bf16.bf16.f32 "
        "{%0,%1,%2,%3}, {%4,%5,%6,%7}, {%8,%9}, {%0,%1,%2,%3};"
        : "+f"(d[0]), "+f"(d[1]), "+f"(d[2]), "+f"(d[3])
        : "r"(a.x), "r"(a.y), "r"(a.z), "r"(a.w), "r"(b0), "r"(b1));
}
// mma.sync m16n8k16 row.col f32.f16.f16.f32
__device__ __forceinline__ void hmma16(float* d, const uint4& a, uint32_t b0, uint32_t b1) {
    asm volatile(
        "mma.sync.aligned.m16n8k16.row.col.f32.f16.f16.f32 "
        "{%0,%1,%2,%3}, {%4,%5,%6,%7}, {%8,%9}, {%0,%1,%2,%3};"
        : "+f"(d[0]), "+f"(d[1]), "+f"(d[2]), "+f"(d[3])
        : "r"(a.x), "r"(a.y), "r"(a.z), "r"(a.w), "r"(b0), "r"(b1));
}

// ---------------------------------------------------------------------------
// K1: xg = x @ w_ih^T + b_ih  via HMMA split-bf16 (3 products). (unchanged)
// ---------------------------------------------------------------------------
__global__ void __launch_bounds__(256, 2)
k1_xg(const float* __restrict__ x, const float* __restrict__ wih,
      const float* __restrict__ bih)
{
    __shared__ uint32_t Bf[2][8][8][32][2];

    const int tid  = threadIdx.x;
    const int wid  = tid >> 5;
    const int lane = tid & 31;
    const int m0 = blockIdx.y * 128;
    const int n0 = blockIdx.x * 64;

    for (int idx = tid; idx < 2 * 8 * 8 * 32; idx += 256) {
        int el = idx & 31;
        int ks = (idx >> 5) & 7;
        int nt = (idx >> 8) & 7;
        int p  = idx >> 11;
        const float* wr = &wih[(n0 + nt * 8 + (el >> 2)) * F_SZ + ks * 16 + (el & 3) * 2];
        float w00 = wr[0], w01 = wr[1], w10 = wr[8], w11 = wr[9];
        if (p) { w00 = bflo(w00); w01 = bflo(w01); w10 = bflo(w10); w11 = bflo(w11); }
        Bf[p][nt][ks][el][0] = pkbf(w00, w01);
        Bf[p][nt][ks][el][1] = pkbf(w10, w11);
    }
    __syncthreads();

    const int mt  = wid;
    const int gid = lane >> 2;
    const int tig = lane & 3;
    const float* xr0 = &x[(m0 + mt * 16 + gid) * F_SZ];
    const float* xr1 = xr0 + 8 * F_SZ;

    float acc[8][4];
#pragma unroll
    for (int nt = 0; nt < 8; nt++)
#pragma unroll
        for (int i = 0; i < 4; i++) acc[nt][i] = 0.f;

#pragma unroll
    for (int ks = 0; ks < 8; ks++) {
        int kc = ks * 16 + tig * 2;
        float2 x00 = *(const float2*)&xr0[kc];
        float2 x10 = *(const float2*)&xr1[kc];
        float2 x01 = *(const float2*)&xr0[kc + 8];
        float2 x11 = *(const float2*)&xr1[kc + 8];
        uint4 ahi = make_uint4(pkbf(x00.x, x00.y), pkbf(x10.x, x10.y),
                               pkbf(x01.x, x01.y), pkbf(x11.x, x11.y));
        uint4 alo = make_uint4(pkbf(bflo(x00.x), bflo(x00.y)),
                               pkbf(bflo(x10.x), bflo(x10.y)),
                               pkbf(bflo(x01.x), bflo(x01.y)),
                               pkbf(bflo(x11.x), bflo(x11.y)));
#pragma unroll
        for (int nt = 0; nt < 8; nt++) {
            uint2 bh = *(const uint2*)&Bf[0][nt][ks][lane][0];
            uint2 bl = *(const uint2*)&Bf[1][nt][ks][lane][0];
            hmma(acc[nt], ahi, bh.x, bh.y);
            hmma(acc[nt], alo, bh.x, bh.y);
            hmma(acc[nt], ahi, bl.x, bl.y);
        }
    }

    const int row0 = m0 + mt * 16 + gid;
#pragma unroll
    for (int nt = 0; nt < 8; nt++) {
        int col = n0 + nt * 8 + tig * 2;
        float2 bb = *(const float2*)&bih[col];
        *(float2*)&g_XG[row0 * G_SZ + col] =
            make_float2(acc[nt][0] + bb.x, acc[nt][1] + bb.y);
        *(float2*)&g_XG[(row0 + 8) * G_SZ + col] =
            make_float2(acc[nt][2] + bb.x, acc[nt][3] + bb.y);
    }
}

// ---------------------------------------------------------------------------
// K2: persistent HMMA GRU recurrence, 256 CTAs (16 batches x 8 j each).
// SINGLE-PRODUCT fp16: hg = h_f16 . W_f16 (f32 accumulate).
// h error 2^-11, W error 2^-11 — more accurate than bf16 2-product.
// Warp w owns ks in [4w, 4w+4): 12 HMMA per warp per step.
// ---------------------------------------------------------------------------
__global__ void __launch_bounds__(NTHR2, 2)
k2_gru(const float* __restrict__ wHH, const float* __restrict__ bHH)
{
    extern __shared__ uint32_t sm[];
    uint32_t* Bsm = sm;
    float*    Dsm = (float*)(sm + BSM_U32);

    const int tid  = threadIdx.x;
    const int wid  = tid >> 5;
    const int lane = tid & 31;
    const int bid  = blockIdx.x;
    const int grp  = bid & 3;
    const int b0   = grp * 16;
    const int j0   = (bid >> 2) * JPC;

    // ---- one-time: W -> fp16 fragments in SMEM (24 real cols) ----
    for (int idx = tid; idx < 3 * 32 * 32; idx += NTHR2) {
        int el = idx & 31;
        int ks = (idx >> 5) & 31;
        int nt = (idx >> 10) % 3;
        int n  = nt * 8 + (el >> 2);
        int jl = n / 3, g = n % 3;
        const float* wr = &wHH[(g * H_SZ + j0 + jl) * H_SZ + ks * 16 + (el & 3) * 2];
        int base = ((nt * 32 + ks) * 32 + el) * 2;
        Bsm[base    ] = pkhf(wr[0], wr[1]);
        Bsm[base + 1] = pkhf(wr[8], wr[9]);
    }

    // ---- epilogue state: threads 0-127 = (batch eb 0..15, j-local jl 0..7) ----
    const int eb = tid >> 3;       // valid for tid < 128
    const int jl = tid & 7;
    float bR = 0.f, bZ = 0.f, bN = 0.f, hprev = 0.f;
    if (tid < 128) {
        bR = __ldg(&bHH[0 * H_SZ + j0 + jl]);
        bZ = __ldg(&bHH[1 * H_SZ + j0 + jl]);
        bN = __ldg(&bHH[2 * H_SZ + j0 + jl]);
    }
    __syncthreads();

    // ---- MMA warp constants ----
    const int ks0 = wid * 4;
    const int gid = lane >> 2;
    const int tig = lane & 3;

    unsigned* arr = &g_arr4[grp][0];

    for (int t = 0; t < T_STEPS; t++) {
        // prefetch xg (independent of h)
        float xr = 0.f, xz = 0.f, xn = 0.f;
        if (tid < 128) {
            const int gbase = (t * B_SZ + b0 + eb) * G_SZ + j0 + jl;
            xr = __ldg(&g_XG[gbase]);
            xz = __ldg(&g_XG[gbase + H_SZ]);
            xn = __ldg(&g_XG[gbase + 2 * H_SZ]);
        }

        if (t > 0) {
            // ---- group barrier: all 64 CTAs of this batch-quarter committed ----
            if (tid == 0) {
                unsigned target = (unsigned)GRPCTA * (unsigned)t;
                unsigned v;
                do {
                    asm volatile("ld.acquire.gpu.u32 %0, [%1];"
                                 : "=r"(v) : "l"(arr) : "memory");
                } while (v < target);
            }
            __syncthreads();

            // ---- MMA phase: 8 warps, 12 HMMA each ----
            const uint32_t* hfr =
                &g_Hfrag[(t + 1) & 1][(grp * 32 + ks0) * 128 + lane * 4];

            uint4 ah[4];
#pragma unroll
            for (int kk = 0; kk < 4; kk++)
                ah[kk] = __ldcg((const uint4*)&hfr[kk * 128]);

            float acc[3][4];
#pragma unroll
            for (int nt = 0; nt < 3; nt++)
#pragma unroll
                for (int i = 0; i < 4; i++) acc[nt][i] = 0.f;

#pragma unroll
            for (int kk = 0; kk < 4; kk++) {
                int ks = ks0 + kk;
#pragma unroll
                for (int nt = 0; nt < 3; nt++) {
                    uint2 bw = *(const uint2*)&Bsm[((nt * 32 + ks) * 32 + lane) * 2];
                    hmma16(acc[nt], ah[kk], bw.x, bw.y);
                }
            }

            // ---- store D partials (slot = warp, 16 rows each) ----
#pragma unroll
            for (int nt = 0; nt < 3; nt++) {
                int col = nt * 8 + tig * 2;
                *(float2*)&Dsm[(wid * 16 + gid) * DST + col] =
                    make_float2(acc[nt][0], acc[nt][1]);
                *(float2*)&Dsm[(wid * 16 + gid + 8) * DST + col] =
                    make_float2(acc[nt][2], acc[nt][3]);
            }
            __syncthreads();
        }

        // ---- epilogue: threads 0-127, one (b, j) each ----
        if (tid < 128) {
            float s0 = 0.f, s1 = 0.f, s2 = 0.f;
            if (t > 0) {
#pragma unroll
                for (int sl = 0; sl < NSLOT; sl++) {
                    const float* pr = &Dsm[(sl * 16 + eb) * DST + jl * 3];
                    s0 += pr[0]; s1 += pr[1]; s2 += pr[2];
                }
            }

            float rr = fsig(xr + s0 + bR);
            float zz = fsig(xz + s1 + bZ);
            float nn = ftanh(xn + rr * (s2 + bN));
            float hnew = (1.0f - zz) * nn + zz * hprev;
            hprev = hnew;

            // h fragment store (fp16)
            float hn1 = __shfl_down_sync(0xffffffffu, hnew, 1);
            if (!(jl & 1)) {
                uint32_t* hw = g_Hfrag[t & 1];
                int r   = b0 + eb;
                int c   = j0 + jl;
                int ks  = c >> 4;
                int lnw = (r & 7) * 4 + ((c >> 1) & 3);
                int reg = (((c >> 3) & 1) << 1) | ((r >> 3) & 1);
                hw[((r >> 4) * 32 + ks) * 128 + lnw * 4 + reg] = pkhf(hnew, hn1);
            }

            g_HS[(t * B_SZ + b0 + eb) * H_SZ + j0 + jl] = hnew;
        }

        __syncthreads();   // all h-frag stores done before release
        if (tid == 0)
            asm volatile("red.release.gpu.add.u32 [%0], %1;"
                         :: "l"(arr), "r"(1u) : "memory");
    }

    // ---- replay-safe per-group counter reset ----
    if (tid == 0) {
        unsigned target = (unsigned)GRPCTA * (unsigned)T_STEPS;
        unsigned v;
        do {
            asm volatile("ld.acquire.gpu.u32 %0, [%1];"
                         : "=r"(v) : "l"(arr) : "memory");
        } while (v < target);
        if (atomicAdd(&g_cnt4[grp][0], 1u) == (unsigned)(GRPCTA - 1)) {
            atomicExch(&g_cnt4[grp][0], 0u);
            atomicExch(&g_arr4[grp][0], 0u);
        }
    }
}

// ---------------------------------------------------------------------------
// K3: y = HS @ w_out^T + b_out   (M=32768, N=16, K=512)
// 64-row tiles, 512 CTAs, high occupancy (latency-bound kernel).
// ---------------------------------------------------------------------------
__global__ void __launch_bounds__(128, 8)
k3_out(const float* __restrict__ wout, const float* __restrict__ bout,
       float* __restrict__ y)
{
    __shared__ float As[32][68];    // As[k][m], 64 rows
    __shared__ float Wsh[32][16];

    const int tid = threadIdx.x;
    const int tx = tid & 3;         // 4 n-groups of 4
    const int ty = tid >> 2;        // 32 m-groups of 2 rows
    const int m0 = blockIdx.x * 64;

    float c[2][4];
#pragma unroll
    for (int i = 0; i < 2; i++)
#pragma unroll
        for (int jj = 0; jj < 4; jj++) c[i][jj] = 0.f;

    for (int kc = 0; kc < H_SZ; kc += 32) {
        __syncthreads();
#pragma unroll
        for (int i = 0; i < 4; i++) {
            int lin = tid + i * 128;           // 0..511
            int m = lin >> 3, k4 = lin & 7;
            float4 v = *(const float4*)&g_HS[(m0 + m) * H_SZ + kc + k4 * 4];
            As[k4 * 4 + 0][m] = v.x; As[k4 * 4 + 1][m] = v.y;
            As[k4 * 4 + 2][m] = v.z; As[k4 * 4 + 3][m] = v.w;
        }
#pragma unroll
        for (int i = 0; i < 4; i++) {
            int lin = tid + i * 128;           // 0..511
            int n = lin >> 5, k = lin & 31;
            Wsh[k][n] = wout[n * H_SZ + kc + k];
        }
        __syncthreads();
#pragma unroll
        for (int k = 0; k < 32; k++) {
            float a[2], w[4];
#pragma unroll
            for (int i = 0; i < 2; i++) a[i] = As[k][ty * 2 + i];
#pragma unroll
            for (int jj = 0; jj < 4; jj++) w[jj] = Wsh[k][tx * 4 + jj];
#pragma unroll
            for (int i = 0; i < 2; i++)
#pragma unroll
                for (int jj = 0; jj < 4; jj++)
                    c[i][jj] = fmaf(a[i], w[jj], c[i][jj]);
        }
    }

    float bb[4];
#pragma unroll
    for (int jj = 0; jj < 4; jj++) bb[jj] = __ldg(&bout[tx * 4 + jj]);
#pragma unroll
    for (int i = 0; i < 2; i++) {
        float4 v;
        v.x = c[i][0] + bb[0]; v.y = c[i][1] + bb[1];
        v.z = c[i][2] + bb[2]; v.w = c[i][3] + bb[3];
        *(float4*)&y[(m0 + ty * 2 + i) * O_SZ + tx * 4] = v;
    }
}

// ---------------------------------------------------------------------------
// Entry point
// ---------------------------------------------------------------------------
extern "C" void kernel_launch(void* const* d_in, const int* in_sizes, int n_in,
                              void* d_out, int out_size)
{
    const float* x    = (const float*)d_in[0];   // (T,B,F)
    const float* wih  = (const float*)d_in[1];   // (3H,F)
    const float* whh  = (const float*)d_in[2];   // (3H,H)
    const float* bih  = (const float*)d_in[3];   // (3H)
    const float* bhh  = (const float*)d_in[4];   // (3H)
    const float* wout = (const float*)d_in[5];   // (O,H)
    const float* bout = (const float*)d_in[6];   // (O)
    float* y = (float*)d_out;                    // (T,B,O)

    cudaFuncSetAttribute(k2_gru, cudaFuncAttributeMaxDynamicSharedMemorySize,
                         SMEM2_BYTES);

    // 1) xg = x @ w_ih^T + b_ih  (HMMA split-bf16, 3 products)
    k1_xg<<<dim3(G_SZ / 64, (T_STEPS * B_SZ) / 128), 256>>>(x, wih, bih);

    // 2) persistent GRU recurrence (HMMA fp16 single-product, 256 CTAs)
    k2_gru<<<NCTA2, NTHR2, SMEM2_BYTES>>>(whh, bhh);

    // 3) output projection (64-row tiles, 512 CTAs)
    k3_out<<<(T_STEPS * B_SZ) / 64, 128>>>(wout, bout, y);
}

// round 12
// speedup vs baseline: 1.3702x; 1.0495x over previous
#include <cuda_runtime.h>
#include <cuda_bf16.h>
#include <cuda_fp16.h>
#include <math.h>
#include <stdint.h>

// Problem constants
#define T_STEPS 512
#define B_SZ    64
#define F_SZ    128
#define H_SZ    512
#define O_SZ    16
#define G_SZ    (3 * H_SZ)   // 1536

// K2 config: 256 CTAs = 4 batch-groups x 64 j-blocks; CTA = 16 batches x 8 j
#define NCTA2   256
#define NTHR2   256
#define JPC     8
#define GRPCTA  64            // CTAs per batch-group
#define NGRP    4

// K2 dynamic SMEM: W fp16 fragments + D exchange
#define BSM_U32     (3 * 32 * 32 * 2)        // 6144 u32 = 24576 B
#define DST         26                       // Dsm row stride (floats)
#define NSLOT       8
#define DSM_FLOATS  (NSLOT * 16 * DST)       // 3328
#define SMEM2_BYTES (BSM_U32 * 4 + DSM_FLOATS * 4)   // 37888

// ---------------------------------------------------------------------------
// Device scratch
// ---------------------------------------------------------------------------
__device__ float g_XG[T_STEPS * B_SZ * G_SZ];       // input-side gate preacts
__device__ float g_HS[T_STEPS * B_SZ * H_SZ];       // hidden states (for K3)
// h (fp16) in HMMA A-fragment layout: [buf][(grp*32 + ks)*128 + lane*4 + reg]
__device__ uint32_t g_Hfrag[2][4 * 32 * 128];
__device__ __align__(128) unsigned g_arr4[NGRP][32];   // per-group arrival counters
__device__ __align__(128) unsigned g_cnt4[NGRP][32];   // per-group reset counters

// ---------------------------------------------------------------------------
// Helpers
// ---------------------------------------------------------------------------
__device__ __forceinline__ float fsig(float x) { return 1.0f / (1.0f + __expf(-x)); }
__device__ __forceinline__ float ftanh(float x) { return 2.0f / (1.0f + __expf(-2.0f * x)) - 1.0f; }

__device__ __forceinline__ uint32_t pkhf(float a, float b) {
    __half2 h = __floats2half2_rn(a, b);
    return *(uint32_t*)&h;
}

// mma.sync m16n8k16 row.col f32.f16.f16.f32
__device__ __forceinline__ void hmma16(float* d, const uint4& a, uint32_t b0, uint32_t b1) {
    asm volatile(
        "mma.sync.aligned.m16n8k16.row.col.f32.f16.f16.f32 "
        "{%0,%1,%2,%3}, {%4,%5,%6,%7}, {%8,%9}, {%0,%1,%2,%3};"
        : "+f"(d[0]), "+f"(d[1]), "+f"(d[2]), "+f"(d[3])
        : "r"(a.x), "r"(a.y), "r"(a.z), "r"(a.w), "r"(b0), "r"(b1));
}

// ---------------------------------------------------------------------------
// K1: xg = x @ w_ih^T + b_ih  via HMMA fp16 single-product.
// ---------------------------------------------------------------------------
__global__ void __launch_bounds__(256, 3)
k1_xg(const float* __restrict__ x, const float* __restrict__ wih,
      const float* __restrict__ bih)
{
    __shared__ uint32_t Bf[8][8][32][2];   // [nt][ks][lane][reg] fp16

    const int tid  = threadIdx.x;
    const int wid  = tid >> 5;
    const int lane = tid & 31;
    const int m0 = blockIdx.y * 128;
    const int n0 = blockIdx.x * 64;

    for (int idx = tid; idx < 8 * 8 * 32; idx += 256) {
        int el = idx & 31;
        int ks = (idx >> 5) & 7;
        int nt = (idx >> 8) & 7;
        const float* wr = &wih[(n0 + nt * 8 + (el >> 2)) * F_SZ + ks * 16 + (el & 3) * 2];
        Bf[nt][ks][el][0] = pkhf(wr[0], wr[1]);
        Bf[nt][ks][el][1] = pkhf(wr[8], wr[9]);
    }
    __syncthreads();

    const int mt  = wid;
    const int gid = lane >> 2;
    const int tig = lane & 3;
    const float* xr0 = &x[(m0 + mt * 16 + gid) * F_SZ];
    const float* xr1 = xr0 + 8 * F_SZ;

    float acc[8][4];
#pragma unroll
    for (int nt = 0; nt < 8; nt++)
#pragma unroll
        for (int i = 0; i < 4; i++) acc[nt][i] = 0.f;

#pragma unroll
    for (int ks = 0; ks < 8; ks++) {
        int kc = ks * 16 + tig * 2;
        float2 x00 = *(const float2*)&xr0[kc];
        float2 x10 = *(const float2*)&xr1[kc];
        float2 x01 = *(const float2*)&xr0[kc + 8];
        float2 x11 = *(const float2*)&xr1[kc + 8];
        uint4 ah = make_uint4(pkhf(x00.x, x00.y), pkhf(x10.x, x10.y),
                              pkhf(x01.x, x01.y), pkhf(x11.x, x11.y));
#pragma unroll
        for (int nt = 0; nt < 8; nt++) {
            uint2 bw = *(const uint2*)&Bf[nt][ks][lane][0];
            hmma16(acc[nt], ah, bw.x, bw.y);
        }
    }

    const int row0 = m0 + mt * 16 + gid;
#pragma unroll
    for (int nt = 0; nt < 8; nt++) {
        int col = n0 + nt * 8 + tig * 2;
        float2 bb = *(const float2*)&bih[col];
        *(float2*)&g_XG[row0 * G_SZ + col] =
            make_float2(acc[nt][0] + bb.x, acc[nt][1] + bb.y);
        *(float2*)&g_XG[(row0 + 8) * G_SZ + col] =
            make_float2(acc[nt][2] + bb.x, acc[nt][3] + bb.y);
    }
}

// ---------------------------------------------------------------------------
// K2: persistent HMMA GRU recurrence, 256 CTAs (16 batches x 8 j each).
// Single-product fp16: hg = h_f16 . W_f16 (f32 accumulate).
// Warp w owns ks in [4w, 4w+4): 12 HMMA per warp per step.
// ---------------------------------------------------------------------------
__global__ void __launch_bounds__(NTHR2, 2)
k2_gru(const float* __restrict__ wHH, const float* __restrict__ bHH)
{
    extern __shared__ uint32_t sm[];
    uint32_t* Bsm = sm;
    float*    Dsm = (float*)(sm + BSM_U32);

    const int tid  = threadIdx.x;
    const int wid  = tid >> 5;
    const int lane = tid & 31;
    const int bid  = blockIdx.x;
    const int grp  = bid & 3;
    const int b0   = grp * 16;
    const int j0   = (bid >> 2) * JPC;

    // ---- one-time: W -> fp16 fragments in SMEM (24 real cols) ----
    for (int idx = tid; idx < 3 * 32 * 32; idx += NTHR2) {
        int el = idx & 31;
        int ks = (idx >> 5) & 31;
        int nt = (idx >> 10) % 3;
        int n  = nt * 8 + (el >> 2);
        int jl = n / 3, g = n % 3;
        const float* wr = &wHH[(g * H_SZ + j0 + jl) * H_SZ + ks * 16 + (el & 3) * 2];
        int base = ((nt * 32 + ks) * 32 + el) * 2;
        Bsm[base    ] = pkhf(wr[0], wr[1]);
        Bsm[base + 1] = pkhf(wr[8], wr[9]);
    }

    // ---- epilogue state: threads 0-127 = (batch eb 0..15, j-local jl 0..7) ----
    const int eb = tid >> 3;       // valid for tid < 128
    const int jl = tid & 7;
    float bR = 0.f, bZ = 0.f, bN = 0.f, hprev = 0.f;
    if (tid < 128) {
        bR = __ldg(&bHH[0 * H_SZ + j0 + jl]);
        bZ = __ldg(&bHH[1 * H_SZ + j0 + jl]);
        bN = __ldg(&bHH[2 * H_SZ + j0 + jl]);
    }
    __syncthreads();

    // ---- MMA warp constants ----
    const int ks0 = wid * 4;
    const int gid = lane >> 2;
    const int tig = lane & 3;

    unsigned* arr = &g_arr4[grp][0];

    for (int t = 0; t < T_STEPS; t++) {
        // prefetch xg (independent of h)
        float xr = 0.f, xz = 0.f, xn = 0.f;
        if (tid < 128) {
            const int gbase = (t * B_SZ + b0 + eb) * G_SZ + j0 + jl;
            xr = __ldg(&g_XG[gbase]);
            xz = __ldg(&g_XG[gbase + H_SZ]);
            xn = __ldg(&g_XG[gbase + 2 * H_SZ]);
        }

        if (t > 0) {
            // ---- group barrier: all 64 CTAs of this batch-quarter committed ----
            if (tid == 0) {
                unsigned target = (unsigned)GRPCTA * (unsigned)t;
                unsigned v;
                do {
                    asm volatile("ld.acquire.gpu.u32 %0, [%1];"
                                 : "=r"(v) : "l"(arr) : "memory");
                } while (v < target);
            }
            __syncthreads();   // release CTA; also protects Dsm reuse

            // ---- MMA phase: 8 warps, 12 HMMA each ----
            const uint32_t* hfr =
                &g_Hfrag[(t + 1) & 1][(grp * 32 + ks0) * 128 + lane * 4];

            uint4 ah[4];
#pragma unroll
            for (int kk = 0; kk < 4; kk++)
                ah[kk] = __ldcg((const uint4*)&hfr[kk * 128]);

            float acc[3][4];
#pragma unroll
            for (int nt = 0; nt < 3; nt++)
#pragma unroll
                for (int i = 0; i < 4; i++) acc[nt][i] = 0.f;

#pragma unroll
            for (int kk = 0; kk < 4; kk++) {
                int ks = ks0 + kk;
#pragma unroll
                for (int nt = 0; nt < 3; nt++) {
                    uint2 bw = *(const uint2*)&Bsm[((nt * 32 + ks) * 32 + lane) * 2];
                    hmma16(acc[nt], ah[kk], bw.x, bw.y);
                }
            }

            // ---- store D partials (slot = warp, 16 rows each) ----
#pragma unroll
            for (int nt = 0; nt < 3; nt++) {
                int col = nt * 8 + tig * 2;
                *(float2*)&Dsm[(wid * 16 + gid) * DST + col] =
                    make_float2(acc[nt][0], acc[nt][1]);
                *(float2*)&Dsm[(wid * 16 + gid + 8) * DST + col] =
                    make_float2(acc[nt][2], acc[nt][3]);
            }
            __syncthreads();
        }

        // ---- epilogue: threads 0-127, one (b, j) each ----
        if (tid < 128) {
            float s0 = 0.f, s1 = 0.f, s2 = 0.f;
            if (t > 0) {
#pragma unroll
                for (int sl = 0; sl < NSLOT; sl++) {
                    const float* pr = &Dsm[(sl * 16 + eb) * DST + jl * 3];
                    s0 += pr[0]; s1 += pr[1]; s2 += pr[2];
                }
            }

            float rr = fsig(xr + s0 + bR);
            float zz = fsig(xz + s1 + bZ);
            float nn = ftanh(xn + rr * (s2 + bN));
            float hnew = (1.0f - zz) * nn + zz * hprev;
            hprev = hnew;

            // h fragment store (fp16)
            float hn1 = __shfl_down_sync(0xffffffffu, hnew, 1);
            if (!(jl & 1)) {
                uint32_t* hw = g_Hfrag[t & 1];
                int r   = b0 + eb;
                int c   = j0 + jl;
                int ks  = c >> 4;
                int lnw = (r & 7) * 4 + ((c >> 1) & 3);
                int reg = (((c >> 3) & 1) << 1) | ((r >> 3) & 1);
                hw[((r >> 4) * 32 + ks) * 128 + lnw * 4 + reg] = pkhf(hnew, hn1);
            }

            // streaming store (read-once by K3; keep L2 for frags/xg)
            __stcs(&g_HS[(t * B_SZ + b0 + eb) * H_SZ + j0 + jl], hnew);

            // 128-thread barrier: h-frag stores (all from threads 0-127)
            // happen-before tid0's release. Warps 4-7 skip to loop-top sync.
            asm volatile("bar.sync 1, 128;" ::: "memory");
            if (tid == 0)
                asm volatile("red.release.gpu.add.u32 [%0], %1;"
                             :: "l"(arr), "r"(1u) : "memory");
        }
    }

    // ---- replay-safe per-group counter reset ----
    __syncthreads();
    if (tid == 0) {
        unsigned target = (unsigned)GRPCTA * (unsigned)T_STEPS;
        unsigned v;
        do {
            asm volatile("ld.acquire.gpu.u32 %0, [%1];"
                         : "=r"(v) : "l"(arr) : "memory");
        } while (v < target);
        if (atomicAdd(&g_cnt4[grp][0], 1u) == (unsigned)(GRPCTA - 1)) {
            atomicExch(&g_cnt4[grp][0], 0u);
            atomicExch(&g_arr4[grp][0], 0u);
        }
    }
}

// ---------------------------------------------------------------------------
// K3: y = HS @ w_out^T + b_out   (M=32768, N=16, K=512)
// 64-row tiles, 512 CTAs, high occupancy (latency-bound kernel).
// ---------------------------------------------------------------------------
__global__ void __launch_bounds__(128, 8)
k3_out(const float* __restrict__ wout, const float* __restrict__ bout,
       float* __restrict__ y)
{
    __shared__ float As[32][68];    // As[k][m], 64 rows
    __shared__ float Wsh[32][16];

    const int tid = threadIdx.x;
    const int tx = tid & 3;         // 4 n-groups of 4
    const int ty = tid >> 2;        // 32 m-groups of 2 rows
    const int m0 = blockIdx.x * 64;

    float c[2][4];
#pragma unroll
    for (int i = 0; i < 2; i++)
#pragma unroll
        for (int jj = 0; jj < 4; jj++) c[i][jj] = 0.f;

    for (int kc = 0; kc < H_SZ; kc += 32) {
        __syncthreads();
#pragma unroll
        for (int i = 0; i < 4; i++) {
            int lin = tid + i * 128;           // 0..511
            int m = lin >> 3, k4 = lin & 7;
            float4 v = *(const float4*)&g_HS[(m0 + m) * H_SZ + kc + k4 * 4];
            As[k4 * 4 + 0][m] = v.x; As[k4 * 4 + 1][m] = v.y;
            As[k4 * 4 + 2][m] = v.z; As[k4 * 4 + 3][m] = v.w;
        }
#pragma unroll
        for (int i = 0; i < 4; i++) {
            int lin = tid + i * 128;           // 0..511
            int n = lin >> 5, k = lin & 31;
            Wsh[k][n] = wout[n * H_SZ + kc + k];
        }
        __syncthreads();
#pragma unroll
        for (int k = 0; k < 32; k++) {
            float a[2], w[4];
#pragma unroll
            for (int i = 0; i < 2; i++) a[i] = As[k][ty * 2 + i];
#pragma unroll
            for (int jj = 0; jj < 4; jj++) w[jj] = Wsh[k][tx * 4 + jj];
#pragma unroll
            for (int i = 0; i < 2; i++)
#pragma unroll
                for (int jj = 0; jj < 4; jj++)
                    c[i][jj] = fmaf(a[i], w[jj], c[i][jj]);
        }
    }

    float bb[4];
#pragma unroll
    for (int jj = 0; jj < 4; jj++) bb[jj] = __ldg(&bout[tx * 4 + jj]);
#pragma unroll
    for (int i = 0; i < 2; i++) {
        float4 v;
        v.x = c[i][0] + bb[0]; v.y = c[i][1] + bb[1];
        v.z = c[i][2] + bb[2]; v.w = c[i][3] + bb[3];
        *(float4*)&y[(m0 + ty * 2 + i) * O_SZ + tx * 4] = v;
    }
}

// ---------------------------------------------------------------------------
// Entry point
// ---------------------------------------------------------------------------
extern "C" void kernel_launch(void* const* d_in, const int* in_sizes, int n_in,
                              void* d_out, int out_size)
{
    const float* x    = (const float*)d_in[0];   // (T,B,F)
    const float* wih  = (const float*)d_in[1];   // (3H,F)
    const float* whh  = (const float*)d_in[2];   // (3H,H)
    const float* bih  = (const float*)d_in[3];   // (3H)
    const float* bhh  = (const float*)d_in[4];   // (3H)
    const float* wout = (const float*)d_in[5];   // (O,H)
    const float* bout = (const float*)d_in[6];   // (O)
    float* y = (float*)d_out;                    // (T,B,O)

    cudaFuncSetAttribute(k2_gru, cudaFuncAttributeMaxDynamicSharedMemorySize,
                         SMEM2_BYTES);

    // 1) xg = x @ w_ih^T + b_ih  (HMMA fp16 single-product)
    k1_xg<<<dim3(G_SZ / 64, (T_STEPS * B_SZ) / 128), 256>>>(x, wih, bih);

    // 2) persistent GRU recurrence (HMMA fp16, 256 CTAs)
    k2_gru<<<NCTA2, NTHR2, SMEM2_BYTES>>>(whh, bhh);

    // 3) output projection (64-row tiles, 512 CTAs)
    k3_out<<<(T_STEPS * B_SZ) / 64, 128>>>(wout, bout, y);
}

// round 13
// speedup vs baseline: 1.4633x; 1.0679x over previous
#include <cuda_runtime.h>
#include <cuda_bf16.h>
#include <cuda_fp16.h>
#include <math.h>
#include <stdint.h>

// Problem constants
#define T_STEPS 512
#define B_SZ    64
#define F_SZ    128
#define H_SZ    512
#define O_SZ    16
#define G_SZ    (3 * H_SZ)   // 1536

// K2 config: 128 CTAs = 2 batch-groups x 64 j-blocks; CTA = 32 batches x 8 j.
// 128 <= 148 SMs -> guaranteed 1 CTA/SM (balanced, no co-residency).
#define NCTA2   128
#define NTHR2   256
#define JPC     8
#define GRPCTA  64            // CTAs per batch-group
#define NGRP    2

// K2 dynamic SMEM: W fp16 fragments + D exchange
#define BSM_U32     (3 * 32 * 32 * 2)        // 6144 u32 = 24576 B
#define DST         26                       // Dsm row stride (floats)
#define NSLOT       4                        // k-quarter slots per m-half
#define DSM_FLOATS  (8 * 16 * DST)           // 3328 (2 m-halves x 4 slots x 16 rows)
#define SMEM2_BYTES (BSM_U32 * 4 + DSM_FLOATS * 4)   // 37888

// ---------------------------------------------------------------------------
// Device scratch
// ---------------------------------------------------------------------------
__device__ float g_XG[T_STEPS * B_SZ * G_SZ];       // input-side gate preacts
__device__ float g_HS[T_STEPS * B_SZ * H_SZ];       // hidden states (for K3)
// h (fp16) in HMMA A-fragment layout: [buf][(mt*32 + ks)*128 + lane*4 + reg]
// mt = global_batch >> 4 (4 m16 tiles cover 64 batches)
__device__ uint32_t g_Hfrag[2][4 * 32 * 128];
__device__ __align__(128) unsigned g_arr4[NGRP][32];   // per-group arrival counters
__device__ __align__(128) unsigned g_cnt4[NGRP][32];   // per-group reset counters

// ---------------------------------------------------------------------------
// Helpers
// ---------------------------------------------------------------------------
__device__ __forceinline__ float fsig(float x) { return 1.0f / (1.0f + __expf(-x)); }
__device__ __forceinline__ float ftanh(float x) { return 2.0f / (1.0f + __expf(-2.0f * x)) - 1.0f; }

__device__ __forceinline__ uint32_t pkhf(float a, float b) {
    __half2 h = __floats2half2_rn(a, b);
    return *(uint32_t*)&h;
}

// mma.sync m16n8k16 row.col f32.f16.f16.f32
__device__ __forceinline__ void hmma16(float* d, const uint4& a, uint32_t b0, uint32_t b1) {
    asm volatile(
        "mma.sync.aligned.m16n8k16.row.col.f32.f16.f16.f32 "
        "{%0,%1,%2,%3}, {%4,%5,%6,%7}, {%8,%9}, {%0,%1,%2,%3};"
        : "+f"(d[0]), "+f"(d[1]), "+f"(d[2]), "+f"(d[3])
        : "r"(a.x), "r"(a.y), "r"(a.z), "r"(a.w), "r"(b0), "r"(b1));
}

// ---------------------------------------------------------------------------
// K1: xg = x @ w_ih^T + b_ih  via HMMA fp16 single-product. (unchanged)
// ---------------------------------------------------------------------------
__global__ void __launch_bounds__(256, 3)
k1_xg(const float* __restrict__ x, const float* __restrict__ wih,
      const float* __restrict__ bih)
{
    __shared__ uint32_t Bf[8][8][32][2];   // [nt][ks][lane][reg] fp16

    const int tid  = threadIdx.x;
    const int wid  = tid >> 5;
    const int lane = tid & 31;
    const int m0 = blockIdx.y * 128;
    const int n0 = blockIdx.x * 64;

    for (int idx = tid; idx < 8 * 8 * 32; idx += 256) {
        int el = idx & 31;
        int ks = (idx >> 5) & 7;
        int nt = (idx >> 8) & 7;
        const float* wr = &wih[(n0 + nt * 8 + (el >> 2)) * F_SZ + ks * 16 + (el & 3) * 2];
        Bf[nt][ks][el][0] = pkhf(wr[0], wr[1]);
        Bf[nt][ks][el][1] = pkhf(wr[8], wr[9]);
    }
    __syncthreads();

    const int mt  = wid;
    const int gid = lane >> 2;
    const int tig = lane & 3;
    const float* xr0 = &x[(m0 + mt * 16 + gid) * F_SZ];
    const float* xr1 = xr0 + 8 * F_SZ;

    float acc[8][4];
#pragma unroll
    for (int nt = 0; nt < 8; nt++)
#pragma unroll
        for (int i = 0; i < 4; i++) acc[nt][i] = 0.f;

#pragma unroll
    for (int ks = 0; ks < 8; ks++) {
        int kc = ks * 16 + tig * 2;
        float2 x00 = *(const float2*)&xr0[kc];
        float2 x10 = *(const float2*)&xr1[kc];
        float2 x01 = *(const float2*)&xr0[kc + 8];
        float2 x11 = *(const float2*)&xr1[kc + 8];
        uint4 ah = make_uint4(pkhf(x00.x, x00.y), pkhf(x10.x, x10.y),
                              pkhf(x01.x, x01.y), pkhf(x11.x, x11.y));
#pragma unroll
        for (int nt = 0; nt < 8; nt++) {
            uint2 bw = *(const uint2*)&Bf[nt][ks][lane][0];
            hmma16(acc[nt], ah, bw.x, bw.y);
        }
    }

    const int row0 = m0 + mt * 16 + gid;
#pragma unroll
    for (int nt = 0; nt < 8; nt++) {
        int col = n0 + nt * 8 + tig * 2;
        float2 bb = *(const float2*)&bih[col];
        *(float2*)&g_XG[row0 * G_SZ + col] =
            make_float2(acc[nt][0] + bb.x, acc[nt][1] + bb.y);
        *(float2*)&g_XG[(row0 + 8) * G_SZ + col] =
            make_float2(acc[nt][2] + bb.x, acc[nt][3] + bb.y);
    }
}

// ---------------------------------------------------------------------------
// K2: persistent HMMA GRU recurrence, 128 CTAs (32 batches x 8 j each),
// guaranteed 1 CTA/SM. Warp (mtl, kh): m-half mtl, k-quarter kh (8 k16),
// 24 HMMA each. D exchange: 4 k-slots per m-half, 12-LDS reduce.
// ---------------------------------------------------------------------------
__global__ void __launch_bounds__(NTHR2, 1)
k2_gru(const float* __restrict__ wHH, const float* __restrict__ bHH)
{
    extern __shared__ uint32_t sm[];
    uint32_t* Bsm = sm;
    float*    Dsm = (float*)(sm + BSM_U32);

    const int tid  = threadIdx.x;
    const int wid  = tid >> 5;
    const int lane = tid & 31;
    const int bid  = blockIdx.x;
    const int grp  = bid & 1;
    const int b0   = grp * 32;
    const int j0   = (bid >> 1) * JPC;

    // ---- one-time: W -> fp16 fragments in SMEM (24 real cols) ----
    for (int idx = tid; idx < 3 * 32 * 32; idx += NTHR2) {
        int el = idx & 31;
        int ks = (idx >> 5) & 31;
        int nt = (idx >> 10) % 3;
        int n  = nt * 8 + (el >> 2);
        int jl = n / 3, g = n % 3;
        const float* wr = &wHH[(g * H_SZ + j0 + jl) * H_SZ + ks * 16 + (el & 3) * 2];
        int base = ((nt * 32 + ks) * 32 + el) * 2;
        Bsm[base    ] = pkhf(wr[0], wr[1]);
        Bsm[base + 1] = pkhf(wr[8], wr[9]);
    }

    // ---- epilogue state: 256 threads = (batch eb 0..31, j-local jl 0..7) ----
    const int eb = tid >> 3;
    const int jl = tid & 7;
    const float bR = __ldg(&bHH[0 * H_SZ + j0 + jl]);
    const float bZ = __ldg(&bHH[1 * H_SZ + j0 + jl]);
    const float bN = __ldg(&bHH[2 * H_SZ + j0 + jl]);
    float hprev = 0.f;
    __syncthreads();

    // ---- MMA warp constants ----
    const int mtl = wid >> 2;              // m-half (16 batches)
    const int kh  = wid & 3;               // k-quarter (8 k16)
    const int mtg = grp * 2 + mtl;         // global m16 tile 0..3
    const int ks0 = kh * 8;
    const int gid = lane >> 2;
    const int tig = lane & 3;

    unsigned* arr = &g_arr4[grp][0];

    for (int t = 0; t < T_STEPS; t++) {
        // prefetch xg (independent of h)
        const int gbase = (t * B_SZ + b0 + eb) * G_SZ + j0 + jl;
        float xr = __ldg(&g_XG[gbase]);
        float xz = __ldg(&g_XG[gbase + H_SZ]);
        float xn = __ldg(&g_XG[gbase + 2 * H_SZ]);

        if (t > 0) {
            // ---- group barrier: all 64 CTAs of this batch-half committed ----
            if (tid == 0) {
                unsigned target = (unsigned)GRPCTA * (unsigned)t;
                unsigned v;
                do {
                    asm volatile("ld.acquire.gpu.u32 %0, [%1];"
                                 : "=r"(v) : "l"(arr) : "memory");
                } while (v < target);
            }
            __syncthreads();   // release CTA; also protects Dsm reuse

            // ---- MMA phase: 8 warps, 24 HMMA each ----
            const uint32_t* hfr =
                &g_Hfrag[(t + 1) & 1][(mtg * 32 + ks0) * 128 + lane * 4];

            uint4 ah[8];
#pragma unroll
            for (int kk = 0; kk < 8; kk++)
                ah[kk] = __ldcg((const uint4*)&hfr[kk * 128]);

            float acc[3][4];
#pragma unroll
            for (int nt = 0; nt < 3; nt++)
#pragma unroll
                for (int i = 0; i < 4; i++) acc[nt][i] = 0.f;

#pragma unroll
            for (int kk = 0; kk < 8; kk++) {
                int ks = ks0 + kk;
#pragma unroll
                for (int nt = 0; nt < 3; nt++) {
                    uint2 bw = *(const uint2*)&Bsm[((nt * 32 + ks) * 32 + lane) * 2];
                    hmma16(acc[nt], ah[kk], bw.x, bw.y);
                }
            }

            // ---- store D partials: slot = mtl*4 + kh (16 rows each) ----
            const int slot = mtl * 4 + kh;
#pragma unroll
            for (int nt = 0; nt < 3; nt++) {
                int col = nt * 8 + tig * 2;
                *(float2*)&Dsm[(slot * 16 + gid) * DST + col] =
                    make_float2(acc[nt][0], acc[nt][1]);
                *(float2*)&Dsm[(slot * 16 + gid + 8) * DST + col] =
                    make_float2(acc[nt][2], acc[nt][3]);
            }
            __syncthreads();
        }

        // ---- epilogue: all 256 threads, one (b, j) each ----
        float s0 = 0.f, s1 = 0.f, s2 = 0.f;
        if (t > 0) {
            const int mh = eb >> 4;            // m-half of this batch
            const int rr = eb & 15;            // row within m16
#pragma unroll
            for (int kq = 0; kq < 4; kq++) {
                const float* pr = &Dsm[((mh * 4 + kq) * 16 + rr) * DST + jl * 3];
                s0 += pr[0]; s1 += pr[1]; s2 += pr[2];
            }
        }

        float rg = fsig(xr + s0 + bR);
        float zg = fsig(xz + s1 + bZ);
        float ng = ftanh(xn + rg * (s2 + bN));
        float hnew = (1.0f - zg) * ng + zg * hprev;
        hprev = hnew;

        // h fragment store (fp16) — the only store the barrier must cover
        float hn1 = __shfl_down_sync(0xffffffffu, hnew, 1);
        if (!(jl & 1)) {
            uint32_t* hw = g_Hfrag[t & 1];
            int r   = b0 + eb;
            int c   = j0 + jl;
            int ks  = c >> 4;
            int lnw = (r & 7) * 4 + ((c >> 1) & 3);
            int reg = (((c >> 3) & 1) << 1) | ((r >> 3) & 1);
            hw[((r >> 4) * 32 + ks) * 128 + lnw * 4 + reg] = pkhf(hnew, hn1);
        }

        __syncthreads();   // h-frag stores happen-before the release
        if (tid == 0)
            asm volatile("red.release.gpu.add.u32 [%0], %1;"
                         :: "l"(arr), "r"(1u) : "memory");

        // off the inter-CTA critical path: fp32 hidden state for K3
        __stcs(&g_HS[(t * B_SZ + b0 + eb) * H_SZ + j0 + jl], hnew);
    }

    // ---- replay-safe per-group counter reset ----
    if (tid == 0) {
        unsigned target = (unsigned)GRPCTA * (unsigned)T_STEPS;
        unsigned v;
        do {
            asm volatile("ld.acquire.gpu.u32 %0, [%1];"
                         : "=r"(v) : "l"(arr) : "memory");
        } while (v < target);
        if (atomicAdd(&g_cnt4[grp][0], 1u) == (unsigned)(GRPCTA - 1)) {
            atomicExch(&g_cnt4[grp][0], 0u);
            atomicExch(&g_arr4[grp][0], 0u);
        }
    }
}

// ---------------------------------------------------------------------------
// K3: y = HS @ w_out^T + b_out   (M=32768, N=16, K=512)
// 64-row tiles, 512 CTAs, high occupancy (latency-bound kernel).
// ---------------------------------------------------------------------------
__global__ void __launch_bounds__(128, 8)
k3_out(const float* __restrict__ wout, const float* __restrict__ bout,
       float* __restrict__ y)
{
    __shared__ float As[32][68];    // As[k][m], 64 rows
    __shared__ float Wsh[32][16];

    const int tid = threadIdx.x;
    const int tx = tid & 3;         // 4 n-groups of 4
    const int ty = tid >> 2;        // 32 m-groups of 2 rows
    const int m0 = blockIdx.x * 64;

    float c[2][4];
#pragma unroll
    for (int i = 0; i < 2; i++)
#pragma unroll
        for (int jj = 0; jj < 4; jj++) c[i][jj] = 0.f;

    for (int kc = 0; kc < H_SZ; kc += 32) {
        __syncthreads();
#pragma unroll
        for (int i = 0; i < 4; i++) {
            int lin = tid + i * 128;           // 0..511
            int m = lin >> 3, k4 = lin & 7;
            float4 v = *(const float4*)&g_HS[(m0 + m) * H_SZ + kc + k4 * 4];
            As[k4 * 4 + 0][m] = v.x; As[k4 * 4 + 1][m] = v.y;
            As[k4 * 4 + 2][m] = v.z; As[k4 * 4 + 3][m] = v.w;
        }
#pragma unroll
        for (int i = 0; i < 4; i++) {
            int lin = tid + i * 128;           // 0..511
            int n = lin >> 5, k = lin & 31;
            Wsh[k][n] = wout[n * H_SZ + kc + k];
        }
        __syncthreads();
#pragma unroll
        for (int k = 0; k < 32; k++) {
            float a[2], w[4];
#pragma unroll
            for (int i = 0; i < 2; i++) a[i] = As[k][ty * 2 + i];
#pragma unroll
            for (int jj = 0; jj < 4; jj++) w[jj] = Wsh[k][tx * 4 + jj];
#pragma unroll
            for (int i = 0; i < 2; i++)
#pragma unroll
                for (int jj = 0; jj < 4; jj++)
                    c[i][jj] = fmaf(a[i], w[jj], c[i][jj]);
        }
    }

    float bb[4];
#pragma unroll
    for (int jj = 0; jj < 4; jj++) bb[jj] = __ldg(&bout[tx * 4 + jj]);
#pragma unroll
    for (int i = 0; i < 2; i++) {
        float4 v;
        v.x = c[i][0] + bb[0]; v.y = c[i][1] + bb[1];
        v.z = c[i][2] + bb[2]; v.w = c[i][3] + bb[3];
        *(float4*)&y[(m0 + ty * 2 + i) * O_SZ + tx * 4] = v;
    }
}

// ---------------------------------------------------------------------------
// Entry point
// ---------------------------------------------------------------------------
extern "C" void kernel_launch(void* const* d_in, const int* in_sizes, int n_in,
                              void* d_out, int out_size)
{
    const float* x    = (const float*)d_in[0];   // (T,B,F)
    const float* wih  = (const float*)d_in[1];   // (3H,F)
    const float* whh  = (const float*)d_in[2];   // (3H,H)
    const float* bih  = (const float*)d_in[3];   // (3H)
    const float* bhh  = (const float*)d_in[4];   // (3H)
    const float* wout = (const float*)d_in[5];   // (O,H)
    const float* bout = (const float*)d_in[6];   // (O)
    float* y = (float*)d_out;                    // (T,B,O)

    cudaFuncSetAttribute(k2_gru, cudaFuncAttributeMaxDynamicSharedMemorySize,
                         SMEM2_BYTES);

    // 1) xg = x @ w_ih^T + b_ih  (HMMA fp16 single-product)
    k1_xg<<<dim3(G_SZ / 64, (T_STEPS * B_SZ) / 128), 256>>>(x, wih, bih);

    // 2) persistent GRU recurrence (HMMA fp16, 128 CTAs, 1/SM balanced)
    k2_gru<<<NCTA2, NTHR2, SMEM2_BYTES>>>(whh, bhh);

    // 3) output projection (64-row tiles, 512 CTAs)
    k3_out<<<(T_STEPS * B_SZ) / 64, 128>>>(wout, bout, y);
}

// round 14
// speedup vs baseline: 1.5687x; 1.0721x over previous
#include <cuda_runtime.h>
#include <cuda_bf16.h>
#include <cuda_fp16.h>
#include <math.h>
#include <stdint.h>

// Problem constants
#define T_STEPS 512
#define B_SZ    64
#define F_SZ    128
#define H_SZ    512
#define O_SZ    16
#define G_SZ    (3 * H_SZ)   // 1536

// K2 config: 128 CTAs = 2 batch-groups x 64 j-blocks; CTA = 32 batches x 8 j.
#define NCTA2   128
#define NTHR2   256
#define JPC     8
#define GRPCTA  64            // CTAs per batch-group
#define NGRP    2

// K2 dynamic SMEM: W fp16 fragments + D exchange
#define BSM_U32     (3 * 32 * 32 * 2)        // 6144 u32 = 24576 B
#define DST         26                       // Dsm row stride (floats)
#define DSM_FLOATS  (8 * 16 * DST)           // 3328
#define SMEM2_BYTES (BSM_U32 * 4 + DSM_FLOATS * 4)   // 37888

#define NTILES_A    2048      // (T*B)/16 m16 tiles of x
#define NTILES_WN   192       // 1536/8 n8 tiles of w_ih

// ---------------------------------------------------------------------------
// Device scratch
// ---------------------------------------------------------------------------
__device__ float g_XG[T_STEPS * B_SZ * G_SZ];       // input-side gate preacts
__device__ float g_HS[T_STEPS * B_SZ * H_SZ];       // hidden states (for K3)
// h (fp16) in HMMA A-fragment layout: [buf][(mt*32 + ks)*128 + lane*4 + reg]
__device__ uint32_t g_Hfrag[2][4 * 32 * 128];
// prepacked fp16 fragments of x (A-side) and w_ih (B-side)
__device__ uint4 g_XF[NTILES_A * 8 * 32];
__device__ uint2 g_WF[NTILES_WN * 8 * 32];
__device__ __align__(128) unsigned g_arr4[NGRP][32];   // per-group arrival counters
__device__ __align__(128) unsigned g_cnt4[NGRP][32];   // per-group reset counters

// ---------------------------------------------------------------------------
// Helpers
// ---------------------------------------------------------------------------
__device__ __forceinline__ float fsig(float x) { return 1.0f / (1.0f + __expf(-x)); }
__device__ __forceinline__ float ftanh(float x) { return 2.0f / (1.0f + __expf(-2.0f * x)) - 1.0f; }

__device__ __forceinline__ uint32_t pkhf(float a, float b) {
    __half2 h = __floats2half2_rn(a, b);
    return *(uint32_t*)&h;
}

// mma.sync m16n8k16 row.col f32.f16.f16.f32
__device__ __forceinline__ void hmma16(float* d, const uint4& a, uint32_t b0, uint32_t b1) {
    asm volatile(
        "mma.sync.aligned.m16n8k16.row.col.f32.f16.f16.f32 "
        "{%0,%1,%2,%3}, {%4,%5,%6,%7}, {%8,%9}, {%0,%1,%2,%3};"
        : "+f"(d[0]), "+f"(d[1]), "+f"(d[2]), "+f"(d[3])
        : "r"(a.x), "r"(a.y), "r"(a.z), "r"(a.w), "r"(b0), "r"(b1));
}

// ---------------------------------------------------------------------------
// k0: prepack x (A-frags) and w_ih (B-frags) as fp16.
// CTAs [0, 2048): one m16 x-tile. CTAs [2048, 2240): one n8 w-tile.
// ---------------------------------------------------------------------------
__global__ void __launch_bounds__(256, 4)
k0_pack(const float* __restrict__ x, const float* __restrict__ wih)
{
    const int tid  = threadIdx.x;
    const int ks   = tid >> 5;
    const int lane = tid & 31;
    const int cb   = blockIdx.x;

    if (cb < NTILES_A) {
        const int row0 = cb * 16 + (lane >> 2);
        const int kc   = ks * 16 + (lane & 3) * 2;
        const float* r0 = &x[row0 * F_SZ + kc];
        const float* r1 = r0 + 8 * F_SZ;
        float2 x00 = *(const float2*)r0;
        float2 x10 = *(const float2*)r1;
        float2 x01 = *(const float2*)(r0 + 8);
        float2 x11 = *(const float2*)(r1 + 8);
        g_XF[(cb * 8 + ks) * 32 + lane] =
            make_uint4(pkhf(x00.x, x00.y), pkhf(x10.x, x10.y),
                       pkhf(x01.x, x01.y), pkhf(x11.x, x11.y));
    } else {
        const int ntg = cb - NTILES_A;
        const int n   = ntg * 8 + (lane >> 2);
        const int kc  = ks * 16 + (lane & 3) * 2;
        const float* wr = &wih[n * F_SZ + kc];
        g_WF[(ntg * 8 + ks) * 32 + lane] =
            make_uint2(pkhf(wr[0], wr[1]), pkhf(wr[8], wr[9]));
    }
}

// ---------------------------------------------------------------------------
// K1: xg = x @ w_ih^T + b_ih via HMMA on prepacked fp16 fragments (SMEM-free).
// Warp = one m16 tile; blockIdx.x = 64-col N block (8 n8 tiles, L1-hot WF).
// ---------------------------------------------------------------------------
__global__ void __launch_bounds__(256, 4)
k1_xg(const float* __restrict__ bih)
{
    const int tid  = threadIdx.x;
    const int wid  = tid >> 5;
    const int lane = tid & 31;
    const int tile = blockIdx.y * 8 + wid;
    const int n0   = blockIdx.x * 64;
    const int ntb  = blockIdx.x * 8;

    float acc[8][4];
#pragma unroll
    for (int nt = 0; nt < 8; nt++)
#pragma unroll
        for (int i = 0; i < 4; i++) acc[nt][i] = 0.f;

#pragma unroll
    for (int ks = 0; ks < 8; ks++) {
        uint4 ah = __ldg(&g_XF[(tile * 8 + ks) * 32 + lane]);
#pragma unroll
        for (int nt = 0; nt < 8; nt++) {
            uint2 bw = __ldg(&g_WF[((ntb + nt) * 8 + ks) * 32 + lane]);
            hmma16(acc[nt], ah, bw.x, bw.y);
        }
    }

    const int gid = lane >> 2;
    const int tig = lane & 3;
    const int row0 = tile * 16 + gid;
#pragma unroll
    for (int nt = 0; nt < 8; nt++) {
        int col = n0 + nt * 8 + tig * 2;
        float2 bb = *(const float2*)&bih[col];
        *(float2*)&g_XG[row0 * G_SZ + col] =
            make_float2(acc[nt][0] + bb.x, acc[nt][1] + bb.y);
        *(float2*)&g_XG[(row0 + 8) * G_SZ + col] =
            make_float2(acc[nt][2] + bb.x, acc[nt][3] + bb.y);
    }
}

// ---------------------------------------------------------------------------
// K2: persistent HMMA GRU recurrence, 128 CTAs (32 batches x 8 j each),
// 1 CTA/SM. Warp (mtl, kh): m-half, k-quarter; 24 HMMA each.
// Poll: 4 pipelined relaxed loads per probe (detect granularity /4).
// ---------------------------------------------------------------------------
__global__ void __launch_bounds__(NTHR2, 1)
k2_gru(const float* __restrict__ wHH, const float* __restrict__ bHH)
{
    extern __shared__ uint32_t sm[];
    uint32_t* Bsm = sm;
    float*    Dsm = (float*)(sm + BSM_U32);

    const int tid  = threadIdx.x;
    const int wid  = tid >> 5;
    const int lane = tid & 31;
    const int bid  = blockIdx.x;
    const int grp  = bid & 1;
    const int b0   = grp * 32;
    const int j0   = (bid >> 1) * JPC;

    // ---- one-time: W -> fp16 fragments in SMEM (24 real cols) ----
    for (int idx = tid; idx < 3 * 32 * 32; idx += NTHR2) {
        int el = idx & 31;
        int ks = (idx >> 5) & 31;
        int nt = (idx >> 10) % 3;
        int n  = nt * 8 + (el >> 2);
        int jl = n / 3, g = n % 3;
        const float* wr = &wHH[(g * H_SZ + j0 + jl) * H_SZ + ks * 16 + (el & 3) * 2];
        int base = ((nt * 32 + ks) * 32 + el) * 2;
        Bsm[base    ] = pkhf(wr[0], wr[1]);
        Bsm[base + 1] = pkhf(wr[8], wr[9]);
    }

    // ---- epilogue state: 256 threads = (batch eb 0..31, j-local jl 0..7) ----
    const int eb = tid >> 3;
    const int jl = tid & 7;
    const float bR = __ldg(&bHH[0 * H_SZ + j0 + jl]);
    const float bZ = __ldg(&bHH[1 * H_SZ + j0 + jl]);
    const float bN = __ldg(&bHH[2 * H_SZ + j0 + jl]);
    float hprev = 0.f;
    __syncthreads();

    // ---- MMA warp constants ----
    const int mtl = wid >> 2;              // m-half (16 batches)
    const int kh  = wid & 3;               // k-quarter (8 k16)
    const int mtg = grp * 2 + mtl;         // global m16 tile 0..3
    const int ks0 = kh * 8;
    const int gid = lane >> 2;
    const int tig = lane & 3;

    unsigned* arr = &g_arr4[grp][0];

    for (int t = 0; t < T_STEPS; t++) {
        // prefetch xg (independent of h)
        const int gbase = (t * B_SZ + b0 + eb) * G_SZ + j0 + jl;
        float xr = __ldg(&g_XG[gbase]);
        float xz = __ldg(&g_XG[gbase + H_SZ]);
        float xn = __ldg(&g_XG[gbase + 2 * H_SZ]);

        if (t > 0) {
            // ---- group barrier: MLP-4 relaxed poll + final acquire ----
            if (tid == 0) {
                unsigned target = (unsigned)GRPCTA * (unsigned)t;
                unsigned v;
                do {
                    unsigned a0, a1, a2, a3;
                    asm volatile(
                        "ld.relaxed.gpu.u32 %0, [%4];\n\t"
                        "ld.relaxed.gpu.u32 %1, [%4];\n\t"
                        "ld.relaxed.gpu.u32 %2, [%4];\n\t"
                        "ld.relaxed.gpu.u32 %3, [%4];"
                        : "=r"(a0), "=r"(a1), "=r"(a2), "=r"(a3)
                        : "l"(arr) : "memory");
                    v = max(max(a0, a1), max(a2, a3));
                } while (v < target);
                asm volatile("ld.acquire.gpu.u32 %0, [%1];"
                             : "=r"(v) : "l"(arr) : "memory");
            }
            __syncthreads();   // release CTA; also protects Dsm reuse

            // ---- MMA phase: 8 warps, 24 HMMA each ----
            const uint32_t* hfr =
                &g_Hfrag[(t + 1) & 1][(mtg * 32 + ks0) * 128 + lane * 4];

            uint4 ah[8];
#pragma unroll
            for (int kk = 0; kk < 8; kk++)
                ah[kk] = __ldcg((const uint4*)&hfr[kk * 128]);

            float acc[3][4];
#pragma unroll
            for (int nt = 0; nt < 3; nt++)
#pragma unroll
                for (int i = 0; i < 4; i++) acc[nt][i] = 0.f;

#pragma unroll
            for (int kk = 0; kk < 8; kk++) {
                int ks = ks0 + kk;
#pragma unroll
                for (int nt = 0; nt < 3; nt++) {
                    uint2 bw = *(const uint2*)&Bsm[((nt * 32 + ks) * 32 + lane) * 2];
                    hmma16(acc[nt], ah[kk], bw.x, bw.y);
                }
            }

            // ---- store D partials: slot = mtl*4 + kh (16 rows each) ----
            const int slot = mtl * 4 + kh;
#pragma unroll
            for (int nt = 0; nt < 3; nt++) {
                int col = nt * 8 + tig * 2;
                *(float2*)&Dsm[(slot * 16 + gid) * DST + col] =
                    make_float2(acc[nt][0], acc[nt][1]);
                *(float2*)&Dsm[(slot * 16 + gid + 8) * DST + col] =
                    make_float2(acc[nt][2], acc[nt][3]);
            }
            __syncthreads();
        }

        // ---- epilogue: all 256 threads, one (b, j) each ----
        float s0 = 0.f, s1 = 0.f, s2 = 0.f;
        if (t > 0) {
            const int mh = eb >> 4;
            const int rr = eb & 15;
#pragma unroll
            for (int kq = 0; kq < 4; kq++) {
                const float* pr = &Dsm[((mh * 4 + kq) * 16 + rr) * DST + jl * 3];
                s0 += pr[0]; s1 += pr[1]; s2 += pr[2];
            }
        }

        float rg = fsig(xr + s0 + bR);
        float zg = fsig(xz + s1 + bZ);
        float ng = ftanh(xn + rg * (s2 + bN));
        float hnew = (1.0f - zg) * ng + zg * hprev;
        hprev = hnew;

        // h fragment store (fp16) — the only store the barrier must cover
        float hn1 = __shfl_down_sync(0xffffffffu, hnew, 1);
        if (!(jl & 1)) {
            uint32_t* hw = g_Hfrag[t & 1];
            int r   = b0 + eb;
            int c   = j0 + jl;
            int ks  = c >> 4;
            int lnw = (r & 7) * 4 + ((c >> 1) & 3);
            int reg = (((c >> 3) & 1) << 1) | ((r >> 3) & 1);
            hw[((r >> 4) * 32 + ks) * 128 + lnw * 4 + reg] = pkhf(hnew, hn1);
        }

        __syncthreads();   // h-frag stores happen-before the release
        if (tid == 0)
            asm volatile("red.release.gpu.add.u32 [%0], %1;"
                         :: "l"(arr), "r"(1u) : "memory");

        // off the inter-CTA critical path: fp32 hidden state for K3
        __stcs(&g_HS[(t * B_SZ + b0 + eb) * H_SZ + j0 + jl], hnew);
    }

    // ---- replay-safe per-group counter reset ----
    if (tid == 0) {
        unsigned target = (unsigned)GRPCTA * (unsigned)T_STEPS;
        unsigned v;
        do {
            asm volatile("ld.acquire.gpu.u32 %0, [%1];"
                         : "=r"(v) : "l"(arr) : "memory");
        } while (v < target);
        if (atomicAdd(&g_cnt4[grp][0], 1u) == (unsigned)(GRPCTA - 1)) {
            atomicExch(&g_cnt4[grp][0], 0u);
            atomicExch(&g_arr4[grp][0], 0u);
        }
    }
}

// ---------------------------------------------------------------------------
// K3: y = HS @ w_out^T + b_out   (M=32768, N=16, K=512)
// ---------------------------------------------------------------------------
__global__ void __launch_bounds__(128, 8)
k3_out(const float* __restrict__ wout, const float* __restrict__ bout,
       float* __restrict__ y)
{
    __shared__ float As[32][68];
    __shared__ float Wsh[32][16];

    const int tid = threadIdx.x;
    const int tx = tid & 3;
    const int ty = tid >> 2;
    const int m0 = blockIdx.x * 64;

    float c[2][4];
#pragma unroll
    for (int i = 0; i < 2; i++)
#pragma unroll
        for (int jj = 0; jj < 4; jj++) c[i][jj] = 0.f;

    for (int kc = 0; kc < H_SZ; kc += 32) {
        __syncthreads();
#pragma unroll
        for (int i = 0; i < 4; i++) {
            int lin = tid + i * 128;
            int m = lin >> 3, k4 = lin & 7;
            float4 v = *(const float4*)&g_HS[(m0 + m) * H_SZ + kc + k4 * 4];
            As[k4 * 4 + 0][m] = v.x; As[k4 * 4 + 1][m] = v.y;
            As[k4 * 4 + 2][m] = v.z; As[k4 * 4 + 3][m] = v.w;
        }
#pragma unroll
        for (int i = 0; i < 4; i++) {
            int lin = tid + i * 128;
            int n = lin >> 5, k = lin & 31;
            Wsh[k][n] = wout[n * H_SZ + kc + k];
        }
        __syncthreads();
#pragma unroll
        for (int k = 0; k < 32; k++) {
            float a[2], w[4];
#pragma unroll
            for (int i = 0; i < 2; i++) a[i] = As[k][ty * 2 + i];
#pragma unroll
            for (int jj = 0; jj < 4; jj++) w[jj] = Wsh[k][tx * 4 + jj];
#pragma unroll
            for (int i = 0; i < 2; i++)
#pragma unroll
                for (int jj = 0; jj < 4; jj++)
                    c[i][jj] = fmaf(a[i], w[jj], c[i][jj]);
        }
    }

    float bb[4];
#pragma unroll
    for (int jj = 0; jj < 4; jj++) bb[jj] = __ldg(&bout[tx * 4 + jj]);
#pragma unroll
    for (int i = 0; i < 2; i++) {
        float4 v;
        v.x = c[i][0] + bb[0]; v.y = c[i][1] + bb[1];
        v.z = c[i][2] + bb[2]; v.w = c[i][3] + bb[3];
        *(float4*)&y[(m0 + ty * 2 + i) * O_SZ + tx * 4] = v;
    }
}

// ---------------------------------------------------------------------------
// Entry point
// ---------------------------------------------------------------------------
extern "C" void kernel_launch(void* const* d_in, const int* in_sizes, int n_in,
                              void* d_out, int out_size)
{
    const float* x    = (const float*)d_in[0];   // (T,B,F)
    const float* wih  = (const float*)d_in[1];   // (3H,F)
    const float* whh  = (const float*)d_in[2];   // (3H,H)
    const float* bih  = (const float*)d_in[3];   // (3H)
    const float* bhh  = (const float*)d_in[4];   // (3H)
    const float* wout = (const float*)d_in[5];   // (O,H)
    const float* bout = (const float*)d_in[6];   // (O)
    float* y = (float*)d_out;                    // (T,B,O)

    cudaFuncSetAttribute(k2_gru, cudaFuncAttributeMaxDynamicSharedMemorySize,
                         SMEM2_BYTES);

    // 0) prepack x and w_ih into fp16 HMMA fragments
    k0_pack<<<NTILES_A + NTILES_WN, 256>>>(x, wih);

    // 1) xg = x @ w_ih^T + b_ih  (HMMA fp16 on prepacked frags)
    k1_xg<<<dim3(G_SZ / 64, NTILES_A / 8), 256>>>(bih);

    // 2) persistent GRU recurrence (HMMA fp16, 128 CTAs, 1/SM)
    k2_gru<<<NCTA2, NTHR2, SMEM2_BYTES>>>(whh, bhh);

    // 3) output projection (64-row tiles, 512 CTAs)
    k3_out<<<(T_STEPS * B_SZ) / 64, 128>>>(wout, bout, y);
}

// round 15
// speedup vs baseline: 1.5693x; 1.0004x over previous
#include <cuda_runtime.h>
#include <cuda_bf16.h>
#include <cuda_fp16.h>
#include <math.h>
#include <stdint.h>

// Problem constants
#define T_STEPS 512
#define B_SZ    64
#define F_SZ    128
#define H_SZ    512
#define O_SZ    16
#define G_SZ    (3 * H_SZ)   // 1536

// K2 config: 128 CTAs = 2 batch-groups x 64 j-blocks; CTA = 32 batches x 8 j.
#define NCTA2   128
#define NTHR2   256
#define JPC     8
#define GRPCTA  64            // CTAs per batch-group
#define NGRP    2

// K2 dynamic SMEM: W fp16 fragments + D exchange
#define BSM_U32     (3 * 32 * 32 * 2)        // 6144 u32 = 24576 B
#define DST         26                       // Dsm row stride (floats)
#define DSM_FLOATS  (8 * 16 * DST)           // 3328
#define SMEM2_BYTES (BSM_U32 * 4 + DSM_FLOATS * 4)   // 37888

#define NTILES_A    2048      // (T*B)/16 m16 tiles of x
#define NTILES_WN   192       // 1536/8 n8 tiles of w_ih

// ---------------------------------------------------------------------------
// Device scratch
// ---------------------------------------------------------------------------
__device__ float g_XG[T_STEPS * B_SZ * G_SZ];       // input-side gate preacts
__device__ float g_HS[T_STEPS * B_SZ * H_SZ];       // hidden states (for K3)
// h (fp16) in HMMA A-fragment layout: [buf][(mt*32 + ks)*128 + lane*4 + reg]
__device__ uint32_t g_Hfrag[2][4 * 32 * 128];
// prepacked fp16 fragments of x (A-side) and w_ih (B-side)
__device__ uint4 g_XF[NTILES_A * 8 * 32];
__device__ uint2 g_WF[NTILES_WN * 8 * 32];
// per-CTA step flags (one 128B line each) + per-group reset counters
__device__ __align__(128) unsigned g_flagsA[NGRP][GRPCTA][32];
__device__ __align__(128) unsigned g_cnt4[NGRP][32];

// ---------------------------------------------------------------------------
// Helpers
// ---------------------------------------------------------------------------
__device__ __forceinline__ float fsig(float x) { return 1.0f / (1.0f + __expf(-x)); }
__device__ __forceinline__ float ftanh(float x) { return 2.0f / (1.0f + __expf(-2.0f * x)) - 1.0f; }

__device__ __forceinline__ uint32_t pkhf(float a, float b) {
    __half2 h = __floats2half2_rn(a, b);
    return *(uint32_t*)&h;
}

// mma.sync m16n8k16 row.col f32.f16.f16.f32
__device__ __forceinline__ void hmma16(float* d, const uint4& a, uint32_t b0, uint32_t b1) {
    asm volatile(
        "mma.sync.aligned.m16n8k16.row.col.f32.f16.f16.f32 "
        "{%0,%1,%2,%3}, {%4,%5,%6,%7}, {%8,%9}, {%0,%1,%2,%3};"
        : "+f"(d[0]), "+f"(d[1]), "+f"(d[2]), "+f"(d[3])
        : "r"(a.x), "r"(a.y), "r"(a.z), "r"(a.w), "r"(b0), "r"(b1));
}

// ---------------------------------------------------------------------------
// k0: prepack x (A-frags) and w_ih (B-frags) as fp16.
// ---------------------------------------------------------------------------
__global__ void __launch_bounds__(256, 4)
k0_pack(const float* __restrict__ x, const float* __restrict__ wih)
{
    const int tid  = threadIdx.x;
    const int ks   = tid >> 5;
    const int lane = tid & 31;
    const int cb   = blockIdx.x;

    if (cb < NTILES_A) {
        const int row0 = cb * 16 + (lane >> 2);
        const int kc   = ks * 16 + (lane & 3) * 2;
        const float* r0 = &x[row0 * F_SZ + kc];
        const float* r1 = r0 + 8 * F_SZ;
        float2 x00 = *(const float2*)r0;
        float2 x10 = *(const float2*)r1;
        float2 x01 = *(const float2*)(r0 + 8);
        float2 x11 = *(const float2*)(r1 + 8);
        g_XF[(cb * 8 + ks) * 32 + lane] =
            make_uint4(pkhf(x00.x, x00.y), pkhf(x10.x, x10.y),
                       pkhf(x01.x, x01.y), pkhf(x11.x, x11.y));
    } else {
        const int ntg = cb - NTILES_A;
        const int n   = ntg * 8 + (lane >> 2);
        const int kc  = ks * 16 + (lane & 3) * 2;
        const float* wr = &wih[n * F_SZ + kc];
        g_WF[(ntg * 8 + ks) * 32 + lane] =
            make_uint2(pkhf(wr[0], wr[1]), pkhf(wr[8], wr[9]));
    }
}

// ---------------------------------------------------------------------------
// K1: xg = x @ w_ih^T + b_ih via HMMA on prepacked fp16 fragments (SMEM-free).
// ---------------------------------------------------------------------------
__global__ void __launch_bounds__(256, 4)
k1_xg(const float* __restrict__ bih)
{
    const int tid  = threadIdx.x;
    const int wid  = tid >> 5;
    const int lane = tid & 31;
    const int tile = blockIdx.y * 8 + wid;
    const int n0   = blockIdx.x * 64;
    const int ntb  = blockIdx.x * 8;

    float acc[8][4];
#pragma unroll
    for (int nt = 0; nt < 8; nt++)
#pragma unroll
        for (int i = 0; i < 4; i++) acc[nt][i] = 0.f;

#pragma unroll
    for (int ks = 0; ks < 8; ks++) {
        uint4 ah = __ldg(&g_XF[(tile * 8 + ks) * 32 + lane]);
#pragma unroll
        for (int nt = 0; nt < 8; nt++) {
            uint2 bw = __ldg(&g_WF[((ntb + nt) * 8 + ks) * 32 + lane]);
            hmma16(acc[nt], ah, bw.x, bw.y);
        }
    }

    const int gid = lane >> 2;
    const int tig = lane & 3;
    const int row0 = tile * 16 + gid;
#pragma unroll
    for (int nt = 0; nt < 8; nt++) {
        int col = n0 + nt * 8 + tig * 2;
        float2 bb = *(const float2*)&bih[col];
        *(float2*)&g_XG[row0 * G_SZ + col] =
            make_float2(acc[nt][0] + bb.x, acc[nt][1] + bb.y);
        *(float2*)&g_XG[(row0 + 8) * G_SZ + col] =
            make_float2(acc[nt][2] + bb.x, acc[nt][3] + bb.y);
    }
}

// ---------------------------------------------------------------------------
// K2: persistent HMMA GRU recurrence, 128 CTAs (32 batches x 8 j each),
// 1 CTA/SM. Dataflow sync: per-CTA step flags; warp kh waits only on the
// 16 CTAs producing its k-quarter's h-frags (per-lane acquire spin).
// ---------------------------------------------------------------------------
__global__ void __launch_bounds__(NTHR2, 1)
k2_gru(const float* __restrict__ wHH, const float* __restrict__ bHH)
{
    extern __shared__ uint32_t sm[];
    uint32_t* Bsm = sm;
    float*    Dsm = (float*)(sm + BSM_U32);

    const int tid  = threadIdx.x;
    const int wid  = tid >> 5;
    const int lane = tid & 31;
    const int bid  = blockIdx.x;
    const int grp  = bid & 1;
    const int b0   = grp * 32;
    const int jblk = bid >> 1;             // j-block index within group
    const int j0   = jblk * JPC;

    // ---- one-time: W -> fp16 fragments in SMEM (24 real cols) ----
    for (int idx = tid; idx < 3 * 32 * 32; idx += NTHR2) {
        int el = idx & 31;
        int ks = (idx >> 5) & 31;
        int nt = (idx >> 10) % 3;
        int n  = nt * 8 + (el >> 2);
        int jl = n / 3, g = n % 3;
        const float* wr = &wHH[(g * H_SZ + j0 + jl) * H_SZ + ks * 16 + (el & 3) * 2];
        int base = ((nt * 32 + ks) * 32 + el) * 2;
        Bsm[base    ] = pkhf(wr[0], wr[1]);
        Bsm[base + 1] = pkhf(wr[8], wr[9]);
    }

    // ---- epilogue state: 256 threads = (batch eb 0..31, j-local jl 0..7) ----
    const int eb = tid >> 3;
    const int jl = tid & 7;
    const float bR = __ldg(&bHH[0 * H_SZ + j0 + jl]);
    const float bZ = __ldg(&bHH[1 * H_SZ + j0 + jl]);
    const float bN = __ldg(&bHH[2 * H_SZ + j0 + jl]);
    float hprev = 0.f;
    __syncthreads();

    // ---- MMA warp constants ----
    const int mtl = wid >> 2;              // m-half (16 batches)
    const int kh  = wid & 3;               // k-quarter (8 k16)
    const int mtg = grp * 2 + mtl;         // global m16 tile 0..3
    const int ks0 = kh * 8;
    const int gid = lane >> 2;
    const int tig = lane & 3;

    // producer flag this lane polls: CTAs jblk = kh*16 + lane (lane < 16)
    const unsigned* myflag = &g_flagsA[grp][kh * 16 + (lane & 15)][0];
    unsigned* ownflag = &g_flagsA[grp][jblk][0];

    for (int t = 0; t < T_STEPS; t++) {
        // prefetch xg (independent of h)
        const int gbase = (t * B_SZ + b0 + eb) * G_SZ + j0 + jl;
        float xr = __ldg(&g_XG[gbase]);
        float xz = __ldg(&g_XG[gbase + H_SZ]);
        float xn = __ldg(&g_XG[gbase + 2 * H_SZ]);

        if (t > 0) {
            // ---- dataflow wait: this warp's 16 producers committed step t ----
            if (lane < 16) {
                unsigned v;
                do {
                    asm volatile("ld.acquire.gpu.u32 %0, [%1];"
                                 : "=r"(v) : "l"(myflag) : "memory");
                } while (v < (unsigned)t);
            }
            __syncwarp();

            // ---- MMA phase: 24 HMMA ----
            const uint32_t* hfr =
                &g_Hfrag[(t + 1) & 1][(mtg * 32 + ks0) * 128 + lane * 4];

            uint4 ah[8];
#pragma unroll
            for (int kk = 0; kk < 8; kk++)
                ah[kk] = __ldcg((const uint4*)&hfr[kk * 128]);

            float acc[3][4];
#pragma unroll
            for (int nt = 0; nt < 3; nt++)
#pragma unroll
                for (int i = 0; i < 4; i++) acc[nt][i] = 0.f;

#pragma unroll
            for (int kk = 0; kk < 8; kk++) {
                int ks = ks0 + kk;
#pragma unroll
                for (int nt = 0; nt < 3; nt++) {
                    uint2 bw = *(const uint2*)&Bsm[((nt * 32 + ks) * 32 + lane) * 2];
                    hmma16(acc[nt], ah[kk], bw.x, bw.y);
                }
            }

            // ---- store D partials: slot = mtl*4 + kh (16 rows each) ----
            const int slot = mtl * 4 + kh;
#pragma unroll
            for (int nt = 0; nt < 3; nt++) {
                int col = nt * 8 + tig * 2;
                *(float2*)&Dsm[(slot * 16 + gid) * DST + col] =
                    make_float2(acc[nt][0], acc[nt][1]);
                *(float2*)&Dsm[(slot * 16 + gid + 8) * DST + col] =
                    make_float2(acc[nt][2], acc[nt][3]);
            }
            __syncthreads();
        }

        // ---- epilogue: all 256 threads, one (b, j) each ----
        float s0 = 0.f, s1 = 0.f, s2 = 0.f;
        if (t > 0) {
            const int mh = eb >> 4;
            const int rr = eb & 15;
#pragma unroll
            for (int kq = 0; kq < 4; kq++) {
                const float* pr = &Dsm[((mh * 4 + kq) * 16 + rr) * DST + jl * 3];
                s0 += pr[0]; s1 += pr[1]; s2 += pr[2];
            }
        }

        float rg = fsig(xr + s0 + bR);
        float zg = fsig(xz + s1 + bZ);
        float ng = ftanh(xn + rg * (s2 + bN));
        float hnew = (1.0f - zg) * ng + zg * hprev;
        hprev = hnew;

        // h fragment store (fp16) — the only store the flag must cover
        float hn1 = __shfl_down_sync(0xffffffffu, hnew, 1);
        if (!(jl & 1)) {
            uint32_t* hw = g_Hfrag[t & 1];
            int r   = b0 + eb;
            int c   = j0 + jl;
            int ks  = c >> 4;
            int lnw = (r & 7) * 4 + ((c >> 1) & 3);
            int reg = (((c >> 3) & 1) << 1) | ((r >> 3) & 1);
            hw[((r >> 4) * 32 + ks) * 128 + lnw * 4 + reg] = pkhf(hnew, hn1);
        }

        __syncthreads();   // h-frag stores + Dsm reads done before release
        if (tid == 0)
            asm volatile("st.release.gpu.u32 [%0], %1;"
                         :: "l"(ownflag), "r"((unsigned)(t + 1)) : "memory");

        // off the inter-CTA critical path: fp32 hidden state for K3
        __stcs(&g_HS[(t * B_SZ + b0 + eb) * H_SZ + j0 + jl], hnew);
    }

    // ---- replay-safe flag reset (last arriver per group resets all) ----
    if (tid == 0) {
        if (atomicAdd(&g_cnt4[grp][0], 1u) == (unsigned)(GRPCTA - 1)) {
            atomicExch(&g_cnt4[grp][0], 0u);
            for (int i = 0; i < GRPCTA; i++)
                g_flagsA[grp][i][0] = 0u;
            __threadfence();
        }
    }
}

// ---------------------------------------------------------------------------
// K3: y = HS @ w_out^T + b_out   (M=32768, N=16, K=512) — 128-row tiles.
// ---------------------------------------------------------------------------
__global__ void __launch_bounds__(128, 4)
k3_out(const float* __restrict__ wout, const float* __restrict__ bout,
       float* __restrict__ y)
{
    __shared__ float As[32][132];
    __shared__ float Wsh[32][16];

    const int tid = threadIdx.x;
    const int tx = tid & 3;
    const int ty = tid >> 2;
    const int m0 = blockIdx.x * 128;

    float c[4][4];
#pragma unroll
    for (int i = 0; i < 4; i++)
#pragma unroll
        for (int jj = 0; jj < 4; jj++) c[i][jj] = 0.f;

    for (int kc = 0; kc < H_SZ; kc += 32) {
        __syncthreads();
#pragma unroll
        for (int i = 0; i < 8; i++) {
            int lin = tid + i * 128;
            int m = lin >> 3, k4 = lin & 7;
            float4 v = *(const float4*)&g_HS[(m0 + m) * H_SZ + kc + k4 * 4];
            As[k4 * 4 + 0][m] = v.x; As[k4 * 4 + 1][m] = v.y;
            As[k4 * 4 + 2][m] = v.z; As[k4 * 4 + 3][m] = v.w;
        }
#pragma unroll
        for (int i = 0; i < 4; i++) {
            int lin = tid + i * 128;
            int n = lin >> 5, k = lin & 31;
            Wsh[k][n] = wout[n * H_SZ + kc + k];
        }
        __syncthreads();
#pragma unroll
        for (int k = 0; k < 32; k++) {
            float a[4], w[4];
#pragma unroll
            for (int i = 0; i < 4; i++) a[i] = As[k][ty * 4 + i];
#pragma unroll
            for (int jj = 0; jj < 4; jj++) w[jj] = Wsh[k][tx * 4 + jj];
#pragma unroll
            for (int i = 0; i < 4; i++)
#pragma unroll
                for (int jj = 0; jj < 4; jj++)
                    c[i][jj] = fmaf(a[i], w[jj], c[i][jj]);
        }
    }

    float bb[4];
#pragma unroll
    for (int jj = 0; jj < 4; jj++) bb[jj] = __ldg(&bout[tx * 4 + jj]);
#pragma unroll
    for (int i = 0; i < 4; i++) {
        float4 v;
        v.x = c[i][0] + bb[0]; v.y = c[i][1] + bb[1];
        v.z = c[i][2] + bb[2]; v.w = c[i][3] + bb[3];
        *(float4*)&y[(m0 + ty * 4 + i) * O_SZ + tx * 4] = v;
    }
}

// ---------------------------------------------------------------------------
// Entry point
// ---------------------------------------------------------------------------
extern "C" void kernel_launch(void* const* d_in, const int* in_sizes, int n_in,
                              void* d_out, int out_size)
{
    const float* x    = (const float*)d_in[0];   // (T,B,F)
    const float* wih  = (const float*)d_in[1];   // (3H,F)
    const float* whh  = (const float*)d_in[2];   // (3H,H)
    const float* bih  = (const float*)d_in[3];   // (3H)
    const float* bhh  = (const float*)d_in[4];   // (3H)
    const float* wout = (const float*)d_in[5];   // (O,H)
    const float* bout = (const float*)d_in[6];   // (O)
    float* y = (float*)d_out;                    // (T,B,O)

    cudaFuncSetAttribute(k2_gru, cudaFuncAttributeMaxDynamicSharedMemorySize,
                         SMEM2_BYTES);

    // 0) prepack x and w_ih into fp16 HMMA fragments
    k0_pack<<<NTILES_A + NTILES_WN, 256>>>(x, wih);

    // 1) xg = x @ w_ih^T + b_ih  (HMMA fp16 on prepacked frags)
    k1_xg<<<dim3(G_SZ / 64, NTILES_A / 8), 256>>>(bih);

    // 2) persistent GRU recurrence (HMMA fp16, dataflow flags)
    k2_gru<<<NCTA2, NTHR2, SMEM2_BYTES>>>(whh, bhh);

    // 3) output projection (128-row tiles)
    k3_out<<<(T_STEPS * B_SZ) / 128, 128>>>(wout, bout, y);
}

// round 16
// speedup vs baseline: 1.6243x; 1.0350x over previous
#include <cuda_runtime.h>
#include <cuda_bf16.h>
#include <cuda_fp16.h>
#include <math.h>
#include <stdint.h>

// Problem constants
#define T_STEPS 512
#define B_SZ    64
#define F_SZ    128
#define H_SZ    512
#define O_SZ    16
#define G_SZ    (3 * H_SZ)   // 1536

// K2 config: 128 CTAs = 2 batch-groups x 64 j-blocks; CTA = 32 batches x 8 j.
// Within a CTA: TWO independent phase-offset pipelines of 16 batches each.
#define NCTA2   128
#define NTHR2   256
#define JPC     8
#define GRPCTA  64            // CTAs per batch-group
#define NGRP    2

// K2 dynamic SMEM: W fp16 fragments + D exchange
#define BSM_U32     (3 * 32 * 32 * 2)        // 6144 u32 = 24576 B
#define DST         26                       // Dsm row stride (floats)
#define DSM_FLOATS  (8 * 16 * DST)           // 3328 (2 halves x 4 k-slots x 16 rows)
#define SMEM2_BYTES (BSM_U32 * 4 + DSM_FLOATS * 4)   // 37888

#define NTILES_A    2048      // (T*B)/16 m16 tiles of x
#define NTILES_WN   192       // 1536/8 n8 tiles of w_ih

// ---------------------------------------------------------------------------
// Device scratch
// ---------------------------------------------------------------------------
__device__ float g_XG[T_STEPS * B_SZ * G_SZ];       // input-side gate preacts
__device__ float g_HS[T_STEPS * B_SZ * H_SZ];       // hidden states (for K3)
// h (fp16) in HMMA A-fragment layout: [buf][(mt*32 + ks)*128 + lane*4 + reg]
// mt = grp*2 + half
__device__ uint32_t g_Hfrag[2][4 * 32 * 128];
// prepacked fp16 fragments of x (A-side) and w_ih (B-side)
__device__ uint4 g_XF[NTILES_A * 8 * 32];
__device__ uint2 g_WF[NTILES_WN * 8 * 32];
// per-(group, half, CTA) step flags (one 128B line each) + reset counters
__device__ __align__(128) unsigned g_flagsB[NGRP][2][GRPCTA][32];
__device__ __align__(128) unsigned g_cntB[NGRP][2][32];

// ---------------------------------------------------------------------------
// Helpers
// ---------------------------------------------------------------------------
__device__ __forceinline__ float fsig(float x) { return 1.0f / (1.0f + __expf(-x)); }
__device__ __forceinline__ float ftanh(float x) { return 2.0f / (1.0f + __expf(-2.0f * x)) - 1.0f; }

__device__ __forceinline__ uint32_t pkhf(float a, float b) {
    __half2 h = __floats2half2_rn(a, b);
    return *(uint32_t*)&h;
}

// mma.sync m16n8k16 row.col f32.f16.f16.f32
__device__ __forceinline__ void hmma16(float* d, const uint4& a, uint32_t b0, uint32_t b1) {
    asm volatile(
        "mma.sync.aligned.m16n8k16.row.col.f32.f16.f16.f32 "
        "{%0,%1,%2,%3}, {%4,%5,%6,%7}, {%8,%9}, {%0,%1,%2,%3};"
        : "+f"(d[0]), "+f"(d[1]), "+f"(d[2]), "+f"(d[3])
        : "r"(a.x), "r"(a.y), "r"(a.z), "r"(a.w), "r"(b0), "r"(b1));
}

// ---------------------------------------------------------------------------
// k0: prepack x (A-frags) and w_ih (B-frags) as fp16.
// ---------------------------------------------------------------------------
__global__ void __launch_bounds__(256, 4)
k0_pack(const float* __restrict__ x, const float* __restrict__ wih)
{
    const int tid  = threadIdx.x;
    const int ks   = tid >> 5;
    const int lane = tid & 31;
    const int cb   = blockIdx.x;

    if (cb < NTILES_A) {
        const int row0 = cb * 16 + (lane >> 2);
        const int kc   = ks * 16 + (lane & 3) * 2;
        const float* r0 = &x[row0 * F_SZ + kc];
        const float* r1 = r0 + 8 * F_SZ;
        float2 x00 = *(const float2*)r0;
        float2 x10 = *(const float2*)r1;
        float2 x01 = *(const float2*)(r0 + 8);
        float2 x11 = *(const float2*)(r1 + 8);
        g_XF[(cb * 8 + ks) * 32 + lane] =
            make_uint4(pkhf(x00.x, x00.y), pkhf(x10.x, x10.y),
                       pkhf(x01.x, x01.y), pkhf(x11.x, x11.y));
    } else {
        const int ntg = cb - NTILES_A;
        const int n   = ntg * 8 + (lane >> 2);
        const int kc  = ks * 16 + (lane & 3) * 2;
        const float* wr = &wih[n * F_SZ + kc];
        g_WF[(ntg * 8 + ks) * 32 + lane] =
            make_uint2(pkhf(wr[0], wr[1]), pkhf(wr[8], wr[9]));
    }
}

// ---------------------------------------------------------------------------
// K1: xg = x @ w_ih^T + b_ih via HMMA on prepacked fp16 fragments (SMEM-free).
// ---------------------------------------------------------------------------
__global__ void __launch_bounds__(256, 4)
k1_xg(const float* __restrict__ bih)
{
    const int tid  = threadIdx.x;
    const int wid  = tid >> 5;
    const int lane = tid & 31;
    const int tile = blockIdx.y * 8 + wid;
    const int n0   = blockIdx.x * 64;
    const int ntb  = blockIdx.x * 8;

    float acc[8][4];
#pragma unroll
    for (int nt = 0; nt < 8; nt++)
#pragma unroll
        for (int i = 0; i < 4; i++) acc[nt][i] = 0.f;

#pragma unroll
    for (int ks = 0; ks < 8; ks++) {
        uint4 ah = __ldg(&g_XF[(tile * 8 + ks) * 32 + lane]);
#pragma unroll
        for (int nt = 0; nt < 8; nt++) {
            uint2 bw = __ldg(&g_WF[((ntb + nt) * 8 + ks) * 32 + lane]);
            hmma16(acc[nt], ah, bw.x, bw.y);
        }
    }

    const int gid = lane >> 2;
    const int tig = lane & 3;
    const int row0 = tile * 16 + gid;
#pragma unroll
    for (int nt = 0; nt < 8; nt++) {
        int col = n0 + nt * 8 + tig * 2;
        float2 bb = *(const float2*)&bih[col];
        *(float2*)&g_XG[row0 * G_SZ + col] =
            make_float2(acc[nt][0] + bb.x, acc[nt][1] + bb.y);
        *(float2*)&g_XG[(row0 + 8) * G_SZ + col] =
            make_float2(acc[nt][2] + bb.x, acc[nt][3] + bb.y);
    }
}

// ---------------------------------------------------------------------------
// K2: persistent HMMA GRU recurrence, 128 CTAs, TWO phase-offset pipelines.
// Pipeline h (h=0: warps 0-3 / threads 0-127; h=1: warps 4-7 / threads
// 128-255) owns 16 batches end-to-end: wait own-half flags -> LDG h-frags ->
// 24 HMMA (k4-split) -> Dsm -> bar.sync(1+h,128) -> gates -> h-frag store ->
// bar.sync(1+h,128) -> release flag[grp][h]. No __syncthreads in the loop;
// the halves hide each other's latency on shared SMSPs.
// ---------------------------------------------------------------------------
__global__ void __launch_bounds__(NTHR2, 1)
k2_gru(const float* __restrict__ wHH, const float* __restrict__ bHH)
{
    extern __shared__ uint32_t sm[];
    uint32_t* Bsm = sm;
    float*    Dsm = (float*)(sm + BSM_U32);

    const int tid  = threadIdx.x;
    const int wid  = tid >> 5;
    const int lane = tid & 31;
    const int bid  = blockIdx.x;
    const int grp  = bid & 1;
    const int b0   = grp * 32;
    const int jblk = bid >> 1;
    const int j0   = jblk * JPC;

    // ---- one-time: W -> fp16 fragments in SMEM (24 real cols) ----
    for (int idx = tid; idx < 3 * 32 * 32; idx += NTHR2) {
        int el = idx & 31;
        int ks = (idx >> 5) & 31;
        int nt = (idx >> 10) % 3;
        int n  = nt * 8 + (el >> 2);
        int jl = n / 3, g = n % 3;
        const float* wr = &wHH[(g * H_SZ + j0 + jl) * H_SZ + ks * 16 + (el & 3) * 2];
        int base = ((nt * 32 + ks) * 32 + el) * 2;
        Bsm[base    ] = pkhf(wr[0], wr[1]);
        Bsm[base + 1] = pkhf(wr[8], wr[9]);
    }

    // ---- per-thread state: (half, batch eb, j-local jl) ----
    const int half = tid >> 7;             // pipeline id
    const int eb   = tid >> 3;             // 0..31 (eb>>4 == half)
    const int jl   = tid & 7;
    const float bR = __ldg(&bHH[0 * H_SZ + j0 + jl]);
    const float bZ = __ldg(&bHH[1 * H_SZ + j0 + jl]);
    const float bN = __ldg(&bHH[2 * H_SZ + j0 + jl]);
    float hprev = 0.f;
    __syncthreads();   // Bsm ready (only sync of the whole loop body)

    // ---- MMA warp constants: warp = (half = wid>>2, kh = wid&3) ----
    const int whalf = wid >> 2;
    const int kh    = wid & 3;
    const int mtg   = grp * 2 + whalf;     // global m16 tile
    const int ks0   = kh * 8;
    const int gid   = lane >> 2;
    const int tig   = lane & 3;

    const unsigned* myflag = &g_flagsB[grp][whalf][kh * 16 + (lane & 15)][0];
    unsigned* ownflag = &g_flagsB[grp][half][jblk][0];

    for (int t = 0; t < T_STEPS; t++) {
        // prefetch xg (independent of h)
        const int gbase = (t * B_SZ + b0 + eb) * G_SZ + j0 + jl;
        float xr = __ldg(&g_XG[gbase]);
        float xz = __ldg(&g_XG[gbase + H_SZ]);
        float xn = __ldg(&g_XG[gbase + 2 * H_SZ]);

        if (t > 0) {
            // ---- wait: this half's 16 producers committed step t ----
            if (lane < 16) {
                unsigned v;
                do {
                    asm volatile("ld.acquire.gpu.u32 %0, [%1];"
                                 : "=r"(v) : "l"(myflag) : "memory");
                } while (v < (unsigned)t);
            }
            __syncwarp();

            // ---- MMA: 24 HMMA on this half's 16 batch rows ----
            const uint32_t* hfr =
                &g_Hfrag[(t + 1) & 1][(mtg * 32 + ks0) * 128 + lane * 4];

            uint4 ah[8];
#pragma unroll
            for (int kk = 0; kk < 8; kk++)
                ah[kk] = __ldcg((const uint4*)&hfr[kk * 128]);

            float acc[3][4];
#pragma unroll
            for (int nt = 0; nt < 3; nt++)
#pragma unroll
                for (int i = 0; i < 4; i++) acc[nt][i] = 0.f;

#pragma unroll
            for (int kk = 0; kk < 8; kk++) {
                int ks = ks0 + kk;
#pragma unroll
                for (int nt = 0; nt < 3; nt++) {
                    uint2 bw = *(const uint2*)&Bsm[((nt * 32 + ks) * 32 + lane) * 2];
                    hmma16(acc[nt], ah[kk], bw.x, bw.y);
                }
            }

            // ---- store D partials: slot = whalf*4 + kh ----
            const int slot = whalf * 4 + kh;
#pragma unroll
            for (int nt = 0; nt < 3; nt++) {
                int col = nt * 8 + tig * 2;
                *(float2*)&Dsm[(slot * 16 + gid) * DST + col] =
                    make_float2(acc[nt][0], acc[nt][1]);
                *(float2*)&Dsm[(slot * 16 + gid + 8) * DST + col] =
                    make_float2(acc[nt][2], acc[nt][3]);
            }
            // half-local barrier (warps of this half only)
            if (whalf == 0) asm volatile("bar.sync 1, 128;" ::: "memory");
            else            asm volatile("bar.sync 2, 128;" ::: "memory");
        }

        // ---- epilogue: threads of this half, one (b, j) each ----
        float s0 = 0.f, s1 = 0.f, s2 = 0.f;
        if (t > 0) {
            const int rr = eb & 15;
#pragma unroll
            for (int kq = 0; kq < 4; kq++) {
                const float* pr = &Dsm[((half * 4 + kq) * 16 + rr) * DST + jl * 3];
                s0 += pr[0]; s1 += pr[1]; s2 += pr[2];
            }
        }

        float rg = fsig(xr + s0 + bR);
        float zg = fsig(xz + s1 + bZ);
        float ng = ftanh(xn + rg * (s2 + bN));
        float hnew = (1.0f - zg) * ng + zg * hprev;
        hprev = hnew;

        // h fragment store (fp16)
        float hn1 = __shfl_down_sync(0xffffffffu, hnew, 1);
        if (!(jl & 1)) {
            uint32_t* hw = g_Hfrag[t & 1];
            int r   = b0 + eb;
            int c   = j0 + jl;
            int ks  = c >> 4;
            int lnw = (r & 7) * 4 + ((c >> 1) & 3);
            int reg = (((c >> 3) & 1) << 1) | ((r >> 3) & 1);
            hw[((r >> 4) * 32 + ks) * 128 + lnw * 4 + reg] = pkhf(hnew, hn1);
        }

        // half-local barrier: h-frag stores + Dsm reads done before release
        if (half == 0) asm volatile("bar.sync 1, 128;" ::: "memory");
        else           asm volatile("bar.sync 2, 128;" ::: "memory");
        if ((tid & 127) == 0)
            asm volatile("st.release.gpu.u32 [%0], %1;"
                         :: "l"(ownflag), "r"((unsigned)(t + 1)) : "memory");

        // off the inter-CTA critical path: fp32 hidden state for K3
        g_HS[(t * B_SZ + b0 + eb) * H_SZ + j0 + jl] = hnew;
    }

    // ---- replay-safe flag reset (last arriver per (grp,half) resets) ----
    if ((tid & 127) == 0) {
        int h = tid >> 7;
        if (atomicAdd(&g_cntB[grp][h][0], 1u) == (unsigned)(GRPCTA - 1)) {
            atomicExch(&g_cntB[grp][h][0], 0u);
            for (int i = 0; i < GRPCTA; i++)
                g_flagsB[grp][h][i][0] = 0u;
            __threadfence();
        }
    }
}

// ---------------------------------------------------------------------------
// K3: y = HS @ w_out^T + b_out   (M=32768, N=16, K=512) — 128-row tiles.
// ---------------------------------------------------------------------------
__global__ void __launch_bounds__(128, 4)
k3_out(const float* __restrict__ wout, const float* __restrict__ bout,
       float* __restrict__ y)
{
    __shared__ float As[32][132];
    __shared__ float Wsh[32][16];

    const int tid = threadIdx.x;
    const int tx = tid & 3;
    const int ty = tid >> 2;
    const int m0 = blockIdx.x * 128;

    float c[4][4];
#pragma unroll
    for (int i = 0; i < 4; i++)
#pragma unroll
        for (int jj = 0; jj < 4; jj++) c[i][jj] = 0.f;

    for (int kc = 0; kc < H_SZ; kc += 32) {
        __syncthreads();
#pragma unroll
        for (int i = 0; i < 8; i++) {
            int lin = tid + i * 128;
            int m = lin >> 3, k4 = lin & 7;
            float4 v = *(const float4*)&g_HS[(m0 + m) * H_SZ + kc + k4 * 4];
            As[k4 * 4 + 0][m] = v.x; As[k4 * 4 + 1][m] = v.y;
            As[k4 * 4 + 2][m] = v.z; As[k4 * 4 + 3][m] = v.w;
        }
#pragma unroll
        for (int i = 0; i < 4; i++) {
            int lin = tid + i * 128;
            int n = lin >> 5, k = lin & 31;
            Wsh[k][n] = wout[n * H_SZ + kc + k];
        }
        __syncthreads();
#pragma unroll
        for (int k = 0; k < 32; k++) {
            float a[4], w[4];
#pragma unroll
            for (int i = 0; i < 4; i++) a[i] = As[k][ty * 4 + i];
#pragma unroll
            for (int jj = 0; jj < 4; jj++) w[jj] = Wsh[k][tx * 4 + jj];
#pragma unroll
            for (int i = 0; i < 4; i++)
#pragma unroll
                for (int jj = 0; jj < 4; jj++)
                    c[i][jj] = fmaf(a[i], w[jj], c[i][jj]);
        }
    }

    float bb[4];
#pragma unroll
    for (int jj = 0; jj < 4; jj++) bb[jj] = __ldg(&bout[tx * 4 + jj]);
#pragma unroll
    for (int i = 0; i < 4; i++) {
        float4 v;
        v.x = c[i][0] + bb[0]; v.y = c[i][1] + bb[1];
        v.z = c[i][2] + bb[2]; v.w = c[i][3] + bb[3];
        *(float4*)&y[(m0 + ty * 4 + i) * O_SZ + tx * 4] = v;
    }
}

// ---------------------------------------------------------------------------
// Entry point
// ---------------------------------------------------------------------------
extern "C" void kernel_launch(void* const* d_in, const int* in_sizes, int n_in,
                              void* d_out, int out_size)
{
    const float* x    = (const float*)d_in[0];   // (T,B,F)
    const float* wih  = (const float*)d_in[1];   // (3H,F)
    const float* whh  = (const float*)d_in[2];   // (3H,H)
    const float* bih  = (const float*)d_in[3];   // (3H)
    const float* bhh  = (const float*)d_in[4];   // (3H)
    const float* wout = (const float*)d_in[5];   // (O,H)
    const float* bout = (const float*)d_in[6];   // (O)
    float* y = (float*)d_out;                    // (T,B,O)

    cudaFuncSetAttribute(k2_gru, cudaFuncAttributeMaxDynamicSharedMemorySize,
                         SMEM2_BYTES);

    // 0) prepack x and w_ih into fp16 HMMA fragments
    k0_pack<<<NTILES_A + NTILES_WN, 256>>>(x, wih);

    // 1) xg = x @ w_ih^T + b_ih  (HMMA fp16 on prepacked frags)
    k1_xg<<<dim3(G_SZ / 64, NTILES_A / 8), 256>>>(bih);

    // 2) persistent GRU recurrence (HMMA fp16, 2 phase-offset pipelines)
    k2_gru<<<NCTA2, NTHR2, SMEM2_BYTES>>>(whh, bhh);

    // 3) output projection (128-row tiles)
    k3_out<<<(T_STEPS * B_SZ) / 128, 128>>>(wout, bout, y);
}